// round 1
// baseline (speedup 1.0000x reference)
#include <cuda_runtime.h>

// Problem dims (fixed by the reference)
#define FD 2048
#define BD 2
#define HD 1024
#define NH 16
#define ED 64
#define D3 3072          // 3*HD
#define MROWS 4096       // FD*BD

// Scratch (static device globals — no allocations allowed)
__device__ float g_qkv[(size_t)MROWS * D3];   // [f*B+b, 3H]
__device__ float g_ctx[(size_t)MROWS * HD];   // [f*B+b, n*64+e]
__device__ int   g_mask_is_int;

// ---------------------------------------------------------------------------
// Mask dtype detector: bool->uint8 vs bool->int32.
// int32 0/1 values have zero bytes at offsets i%4 != 0; random bool bytes don't.
// ---------------------------------------------------------------------------
__global__ void detect_mask_kernel(const unsigned char* __restrict__ m) {
    __shared__ int cnt;
    if (threadIdx.x == 0) cnt = 0;
    __syncthreads();
    int local = 0;
    for (int i = threadIdx.x; i < 65536; i += blockDim.x)
        if ((i & 3) && m[i]) local++;
    if (local) atomicAdd(&cnt, local);
    __syncthreads();
    if (threadIdx.x == 0) g_mask_is_int = (cnt == 0) ? 1 : 0;
}

// ---------------------------------------------------------------------------
// Tiled SGEMM: C[M,Nc] = A[M,K] * B[K,Nc] (+ bias[Nc]), all row-major.
// BM=BN=64, BK=16, 256 threads, 4x4 register tiles. Dims assumed %64 / %16.
// ---------------------------------------------------------------------------
__global__ void __launch_bounds__(256) sgemm_bias_kernel(
    const float* __restrict__ A, const float* __restrict__ B,
    const float* __restrict__ bias, float* __restrict__ C,
    int M, int Nc, int K)
{
    __shared__ float As[16][68];
    __shared__ float Bs[16][68];
    const int tid = threadIdx.x;
    const int tx = tid & 15, ty = tid >> 4;
    const int row0 = blockIdx.y * 64;
    const int col0 = blockIdx.x * 64;

    const int ar = tid >> 2, ac = (tid & 3) << 2;   // A: 64 rows x 16 k
    const int br = tid >> 4, bc = (tid & 15) << 2;  // B: 16 k x 64 cols

    float acc[4][4] = {};
    for (int k0 = 0; k0 < K; k0 += 16) {
        float4 a4 = *(const float4*)&A[(size_t)(row0 + ar) * K + k0 + ac];
        As[ac + 0][ar] = a4.x; As[ac + 1][ar] = a4.y;
        As[ac + 2][ar] = a4.z; As[ac + 3][ar] = a4.w;
        float4 b4 = *(const float4*)&B[(size_t)(k0 + br) * Nc + col0 + bc];
        *(float4*)&Bs[br][bc] = b4;
        __syncthreads();
        #pragma unroll
        for (int k = 0; k < 16; k++) {
            float4 ra = *(const float4*)&As[k][ty << 2];
            float4 rb = *(const float4*)&Bs[k][tx << 2];
            float av[4] = {ra.x, ra.y, ra.z, ra.w};
            float bv[4] = {rb.x, rb.y, rb.z, rb.w};
            #pragma unroll
            for (int i = 0; i < 4; i++)
                #pragma unroll
                for (int j = 0; j < 4; j++)
                    acc[i][j] += av[i] * bv[j];
        }
        __syncthreads();
    }
    #pragma unroll
    for (int i = 0; i < 4; i++) {
        const int r = row0 + (ty << 2) + i;
        const int c = col0 + (tx << 2);
        float4 o = make_float4(acc[i][0], acc[i][1], acc[i][2], acc[i][3]);
        if (bias) {
            float4 bb = *(const float4*)&bias[c];
            o.x += bb.x; o.y += bb.y; o.z += bb.z; o.w += bb.w;
        }
        *(float4*)&C[(size_t)r * Nc + c] = o;
    }
}

// ---------------------------------------------------------------------------
// Flash attention: one block per (f-tile of 64, b*n). BT=64, E=64.
// Online softmax; S tile staged in smem; mask applied from global.
// ---------------------------------------------------------------------------
#define LDSN 68
#define FLASH_SMEM_FLOATS (4 * 64 * LDSN + 3 * 64)
#define FLASH_SMEM_BYTES  (FLASH_SMEM_FLOATS * 4)

__global__ void __launch_bounds__(256) flash_attn_kernel(
    const float* __restrict__ qkv, const void* __restrict__ maskp,
    float* __restrict__ ctx)
{
    extern __shared__ float sm[];
    float* Qs  = sm;
    float* Ks  = Qs + 64 * LDSN;
    float* Vs  = Ks + 64 * LDSN;
    float* Ss  = Vs + 64 * LDSN;
    float* m_s = Ss + 64 * LDSN;
    float* l_s = m_s + 64;
    float* a_s = l_s + 64;

    const int tid = threadIdx.x;
    const int tx = tid & 15, ty = tid >> 4;
    const int bn = blockIdx.y;
    const int b = bn >> 4, n = bn & 15;
    const int f0 = blockIdx.x << 6;
    const int maskIsInt = g_mask_is_int;
    const float scale = 0.125f;   // 1/sqrt(64)

    // cooperative tile loader mapping: 4 threads per row, 16 floats each
    const int lr = tid >> 2;
    const int lc = (tid & 3) << 4;

    { // load Q tile [64 rows f, 64 cols e]
        const float* src = qkv + (size_t)((f0 + lr) * BD + b) * D3 + n * 192;
        #pragma unroll
        for (int c = 0; c < 16; c += 4)
            *(float4*)&Qs[lr * LDSN + lc + c] = *(const float4*)&src[lc + c];
    }
    if (tid < 64) { m_s[tid] = -1e30f; l_s[tid] = 0.f; }

    float acc[4][4] = {};

    for (int t0 = 0; t0 < FD; t0 += 64) {
        __syncthreads();  // protect Ks/Vs/Ss reuse (also covers Q/m/l init)
        { // load K,V tiles for this t-block
            const float* srcK = qkv + (size_t)((t0 + lr) * BD + b) * D3 + n * 192 + 64;
            const float* srcV = srcK + 64;
            #pragma unroll
            for (int c = 0; c < 16; c += 4) {
                *(float4*)&Ks[lr * LDSN + lc + c] = *(const float4*)&srcK[lc + c];
                *(float4*)&Vs[lr * LDSN + lc + c] = *(const float4*)&srcV[lc + c];
            }
        }
        __syncthreads();

        // S = Q K^T  (thread tile: rows ty*4.., cols tx*4..)
        float s[4][4] = {};
        #pragma unroll
        for (int e = 0; e < 64; e += 4) {
            float4 q[4], k[4];
            #pragma unroll
            for (int i = 0; i < 4; i++) q[i] = *(const float4*)&Qs[(ty*4+i)*LDSN + e];
            #pragma unroll
            for (int j = 0; j < 4; j++) k[j] = *(const float4*)&Ks[(tx*4+j)*LDSN + e];
            #pragma unroll
            for (int i = 0; i < 4; i++)
                #pragma unroll
                for (int j = 0; j < 4; j++)
                    s[i][j] += q[i].x*k[j].x + q[i].y*k[j].y + q[i].z*k[j].z + q[i].w*k[j].w;
        }

        // mask + scale -> Ss
        #pragma unroll
        for (int i = 0; i < 4; i++) {
            const int fi = f0 + ty*4 + i;
            const size_t mrow = ((size_t)b * FD + fi) * FD + t0 + tx*4;
            float v0, v1, v2, v3;
            if (maskIsInt) {
                const int4 mi = *(const int4*)((const int*)maskp + mrow);
                v0 = mi.x ? s[i][0]*scale : -10000.f;
                v1 = mi.y ? s[i][1]*scale : -10000.f;
                v2 = mi.z ? s[i][2]*scale : -10000.f;
                v3 = mi.w ? s[i][3]*scale : -10000.f;
            } else {
                const uchar4 mi = *(const uchar4*)((const unsigned char*)maskp + mrow);
                v0 = mi.x ? s[i][0]*scale : -10000.f;
                v1 = mi.y ? s[i][1]*scale : -10000.f;
                v2 = mi.z ? s[i][2]*scale : -10000.f;
                v3 = mi.w ? s[i][3]*scale : -10000.f;
            }
            *(float4*)&Ss[(ty*4+i)*LDSN + tx*4] = make_float4(v0, v1, v2, v3);
        }
        __syncthreads();

        // online softmax over the 64-wide tile (4 threads per row)
        {
            const int row = tid >> 2;
            const int seg = (tid & 3) << 4;
            float mx = -1e30f;
            #pragma unroll
            for (int j = 0; j < 16; j++) mx = fmaxf(mx, Ss[row*LDSN + seg + j]);
            mx = fmaxf(mx, __shfl_xor_sync(0xffffffffu, mx, 1));
            mx = fmaxf(mx, __shfl_xor_sync(0xffffffffu, mx, 2));
            const float m_old = m_s[row];
            const float m_new = fmaxf(m_old, mx);
            float sum = 0.f;
            #pragma unroll
            for (int j = 0; j < 16; j++) {
                const float p = __expf(Ss[row*LDSN + seg + j] - m_new);
                Ss[row*LDSN + seg + j] = p;
                sum += p;
            }
            sum += __shfl_xor_sync(0xffffffffu, sum, 1);
            sum += __shfl_xor_sync(0xffffffffu, sum, 2);
            if ((tid & 3) == 0) {
                const float alpha = __expf(m_old - m_new);
                a_s[row] = alpha;
                l_s[row] = l_s[row] * alpha + sum;
                m_s[row] = m_new;
            }
        }
        __syncthreads();

        // acc = acc*alpha + P @ V  (thread tile: rows ty*4.., e-cols tx*4..)
        float al[4];
        #pragma unroll
        for (int i = 0; i < 4; i++) al[i] = a_s[ty*4+i];
        #pragma unroll
        for (int i = 0; i < 4; i++)
            #pragma unroll
            for (int j = 0; j < 4; j++) acc[i][j] *= al[i];

        #pragma unroll
        for (int t = 0; t < 64; t += 4) {
            float4 p[4], v[4];
            #pragma unroll
            for (int i = 0; i < 4; i++) p[i] = *(const float4*)&Ss[(ty*4+i)*LDSN + t];
            #pragma unroll
            for (int k = 0; k < 4; k++) v[k] = *(const float4*)&Vs[(t+k)*LDSN + tx*4];
            float pv[4][4], vv[4][4];
            #pragma unroll
            for (int i = 0; i < 4; i++) {
                pv[i][0]=p[i].x; pv[i][1]=p[i].y; pv[i][2]=p[i].z; pv[i][3]=p[i].w;
            }
            #pragma unroll
            for (int k = 0; k < 4; k++) {
                vv[k][0]=v[k].x; vv[k][1]=v[k].y; vv[k][2]=v[k].z; vv[k][3]=v[k].w;
            }
            #pragma unroll
            for (int i = 0; i < 4; i++)
                #pragma unroll
                for (int j = 0; j < 4; j++)
                    #pragma unroll
                    for (int k = 0; k < 4; k++)
                        acc[i][j] += pv[i][k] * vv[k][j];
        }
    }

    // normalize + store ctx[f,b, n*64+e]
    float inv[4];
    #pragma unroll
    for (int i = 0; i < 4; i++) inv[i] = 1.0f / l_s[ty*4+i];
    #pragma unroll
    for (int i = 0; i < 4; i++) {
        const int fi = f0 + ty*4 + i;
        float4 o = make_float4(acc[i][0]*inv[i], acc[i][1]*inv[i],
                               acc[i][2]*inv[i], acc[i][3]*inv[i]);
        *(float4*)&ctx[(size_t)(fi * BD + b) * HD + n * 64 + tx*4] = o;
    }
}

// ---------------------------------------------------------------------------
__global__ void copy_tail_kernel(const float* __restrict__ src,
                                 float* __restrict__ dst, int count) {
    const int i = blockIdx.x * blockDim.x + threadIdx.x;
    if (i < count) dst[i] = src[i];
}

// ---------------------------------------------------------------------------
extern "C" void kernel_launch(void* const* d_in, const int* in_sizes, int n_in,
                              void* d_out, int out_size)
{
    const float* q_input = (const float*)d_in[0];
    const void*  mask    = d_in[1];
    const float* w_qkv   = (const float*)d_in[2];
    const float* b_qkv   = (const float*)d_in[3];
    const float* w_out   = (const float*)d_in[4];
    const float* b_out   = (const float*)d_in[5];
    float* out = (float*)d_out;

    float *qkv = nullptr, *ctx = nullptr;
    cudaGetSymbolAddress((void**)&qkv, g_qkv);
    cudaGetSymbolAddress((void**)&ctx, g_ctx);

    // 0) mask dtype probe
    detect_mask_kernel<<<1, 256>>>((const unsigned char*)mask);

    // 1) QKV projection: [4096,1024] x [1024,3072] + bias
    {
        dim3 grid(D3 / 64, MROWS / 64);
        sgemm_bias_kernel<<<grid, 256>>>(q_input, w_qkv, b_qkv, qkv,
                                         MROWS, D3, HD);
    }

    // 2) flash attention per (f-tile, b*n)
    {
        cudaFuncSetAttribute(flash_attn_kernel,
                             cudaFuncAttributeMaxDynamicSharedMemorySize,
                             FLASH_SMEM_BYTES);
        dim3 grid(FD / 64, BD * NH);
        flash_attn_kernel<<<grid, 256, FLASH_SMEM_BYTES>>>(qkv, mask, ctx);
    }

    // 3) output projection: [4096,1024] x [1024,1024] -> d_out (no bias)
    {
        dim3 grid(HD / 64, MROWS / 64);
        sgemm_bias_kernel<<<grid, 256>>>(ctx, w_out, nullptr, out,
                                         MROWS, HD, HD);
    }

    // 4) tuple tail: b_out appended after the [F,B,H] output
    const int main_elems = MROWS * HD;
    const int tail = out_size - main_elems;
    if (tail > 0) {
        copy_tail_kernel<<<(tail + 255) / 256, 256>>>(b_out, out + main_elems, tail);
    }
}

// round 6
// speedup vs baseline: 1.2229x; 1.2229x over previous
#include <cuda_runtime.h>
#include <cuda_bf16.h>
#include <cstdint>

// Problem dims (fixed by the reference)
#define FD 2048
#define BD 2
#define HD 1024
#define NH 16
#define ED 64
#define D3 3072          // 3*HD
#define MROWS 4096       // FD*BD

// ---------------------------------------------------------------------------
// Scratch (static device globals — no allocations allowed)
// ---------------------------------------------------------------------------
__device__ float g_qkv[(size_t)MROWS * D3];   // [f*B+b, 3H] fp32
__device__ float g_ctx[(size_t)MROWS * HD];   // [f*B+b, n*64+e] fp32
__device__ __nv_bfloat16 g_wqkvT_hi[(size_t)D3 * HD];  // W^T [3072,1024]
__device__ __nv_bfloat16 g_wqkvT_lo[(size_t)D3 * HD];
__device__ __nv_bfloat16 g_woutT_hi[(size_t)HD * HD];  // W^T [1024,1024]
__device__ __nv_bfloat16 g_woutT_lo[(size_t)HD * HD];
__device__ int g_mask_is_int;

// ---------------------------------------------------------------------------
// f32x2 packed FMA helpers (FFMA2 — PTX-only; accepted on plain sm_103)
// ---------------------------------------------------------------------------
typedef unsigned long long u64;
__device__ __forceinline__ u64 fma2(u64 a, u64 b, u64 c) {
    u64 d; asm("fma.rn.f32x2 %0, %1, %2, %3;" : "=l"(d) : "l"(a), "l"(b), "l"(c));
    return d;
}
__device__ __forceinline__ u64 mul2(u64 a, u64 b) {
    u64 d; asm("mul.rn.f32x2 %0, %1, %2;" : "=l"(d) : "l"(a), "l"(b));
    return d;
}
__device__ __forceinline__ u64 pack2(float a, float b) {
    u64 d; asm("mov.b64 %0, {%1, %2};" : "=l"(d) : "f"(a), "f"(b));
    return d;
}
__device__ __forceinline__ void unpack2(u64 a, float& x, float& y) {
    asm("mov.b64 {%0, %1}, %2;" : "=f"(x), "=f"(y) : "l"(a));
}
__device__ __forceinline__ uint32_t pbf2(__nv_bfloat16 a, __nv_bfloat16 b) {
    __nv_bfloat162 t = __halves2bfloat162(a, b);
    return *reinterpret_cast<uint32_t*>(&t);
}

// m16n8k16 bf16 MMA, fp32 accumulate (HMMA path — no arch-suffix gating)
__device__ __forceinline__ void mma_bf16(float* d, const uint32_t* a,
                                         const uint32_t* b) {
    asm volatile(
        "mma.sync.aligned.m16n8k16.row.col.f32.bf16.bf16.f32 "
        "{%0,%1,%2,%3}, {%4,%5,%6,%7}, {%8,%9}, {%0,%1,%2,%3};"
        : "+f"(d[0]), "+f"(d[1]), "+f"(d[2]), "+f"(d[3])
        : "r"(a[0]), "r"(a[1]), "r"(a[2]), "r"(a[3]), "r"(b[0]), "r"(b[1]));
}

// ---------------------------------------------------------------------------
// Mask dtype detector: bool->uint8 vs bool->int32
// ---------------------------------------------------------------------------
__global__ void detect_mask_kernel(const unsigned char* __restrict__ m) {
    __shared__ int cnt;
    if (threadIdx.x == 0) cnt = 0;
    __syncthreads();
    int local = 0;
    for (int i = threadIdx.x; i < 65536; i += blockDim.x)
        if ((i & 3) && m[i]) local++;
    if (local) atomicAdd(&cnt, local);
    __syncthreads();
    if (threadIdx.x == 0) g_mask_is_int = (cnt == 0) ? 1 : 0;
}

// ---------------------------------------------------------------------------
// Transpose + hi/lo bf16 split:  W[K,Nc] fp32 -> Th/Tl[Nc,K] bf16
// ---------------------------------------------------------------------------
__global__ void __launch_bounds__(256) transpose_split_kernel(
    const float* __restrict__ W, __nv_bfloat16* __restrict__ Th,
    __nv_bfloat16* __restrict__ Tl, int K, int Nc)
{
    __shared__ float tile[32][33];
    const int tx = threadIdx.x & 31, ty = threadIdx.x >> 5;  // ty 0..7
    const int n0 = blockIdx.x * 32, k0 = blockIdx.y * 32;
    #pragma unroll
    for (int j = 0; j < 32; j += 8)
        tile[ty + j][tx] = W[(size_t)(k0 + ty + j) * Nc + n0 + tx];
    __syncthreads();
    #pragma unroll
    for (int j = 0; j < 32; j += 8) {
        float v = tile[tx][ty + j];
        __nv_bfloat16 h = __float2bfloat16(v);
        __nv_bfloat16 l = __float2bfloat16(v - __bfloat162float(h));
        size_t o = (size_t)(n0 + ty + j) * K + k0 + tx;
        Th[o] = h;
        Tl[o] = l;
    }
}

// ---------------------------------------------------------------------------
// mma.sync GEMM: C[M,Nc] = A[M,K](fp32, split inline) * BT[Nc,K]^T (bf16 hi/lo)
// CTA 128x128, BK=32, 8 warps of 64x32. 3-term bf16-split accumulation.
// smem rows padded to 40 bf16 (80B = 20 banks): fragment loads conflict-free.
// ---------------------------------------------------------------------------
#define ASTR 40

__global__ void __launch_bounds__(256) mma_gemm_kernel(
    const float* __restrict__ A,
    const __nv_bfloat16* __restrict__ BTh,
    const __nv_bfloat16* __restrict__ BTl,
    const float* __restrict__ bias,
    float* __restrict__ C, int M, int Nc, int K)
{
    __shared__ __nv_bfloat16 Ah[128][ASTR], Al[128][ASTR];
    __shared__ __nv_bfloat16 Bh[128][ASTR], Bl[128][ASTR];

    const int tid = threadIdx.x, wid = tid >> 5, lane = tid & 31;
    const int wm = wid & 1, wn = wid >> 1;           // warp tile: 64(M) x 32(N)
    const int m0 = blockIdx.y << 7, n0 = blockIdx.x << 7;
    const int bg = lane >> 2, bc = (lane & 3) << 1;  // fragment lane mapping

    // loader mapping: 2 threads per row, 16 elems each
    const int lr = tid >> 1;
    const int lh = (tid & 1) << 4;
    const float* Ap = A + (size_t)(m0 + lr) * K + lh;
    const __nv_bfloat16* Bhp = BTh + (size_t)(n0 + lr) * K + lh;
    const __nv_bfloat16* Blp = BTl + (size_t)(n0 + lr) * K + lh;

    float acc[4][4][4] = {};   // [mi][ni][c]

    for (int k0 = 0; k0 < K; k0 += 32) {
        __syncthreads();
        // A: fp32 -> hi/lo bf16 split, store to smem
        #pragma unroll
        for (int i = 0; i < 4; i++) {
            float4 x = *(const float4*)(Ap + k0 + (i << 2));
            __nv_bfloat16 h0 = __float2bfloat16(x.x), h1 = __float2bfloat16(x.y);
            __nv_bfloat16 h2 = __float2bfloat16(x.z), h3 = __float2bfloat16(x.w);
            __nv_bfloat16 l0 = __float2bfloat16(x.x - __bfloat162float(h0));
            __nv_bfloat16 l1 = __float2bfloat16(x.y - __bfloat162float(h1));
            __nv_bfloat16 l2 = __float2bfloat16(x.z - __bfloat162float(h2));
            __nv_bfloat16 l3 = __float2bfloat16(x.w - __bfloat162float(h3));
            *(uint2*)&Ah[lr][lh + (i << 2)] = make_uint2(pbf2(h0, h1), pbf2(h2, h3));
            *(uint2*)&Al[lr][lh + (i << 2)] = make_uint2(pbf2(l0, l1), pbf2(l2, l3));
        }
        // B: already bf16 hi/lo in gmem (pre-transposed)
        *(uint4*)&Bh[lr][lh] = *(const uint4*)(Bhp + k0);
        *(uint4*)&Bh[lr][lh + 8] = *(const uint4*)(Bhp + k0 + 8);
        *(uint4*)&Bl[lr][lh] = *(const uint4*)(Blp + k0);
        *(uint4*)&Bl[lr][lh + 8] = *(const uint4*)(Blp + k0 + 8);
        __syncthreads();

        #pragma unroll
        for (int ks = 0; ks < 32; ks += 16) {
            uint32_t bhf[4][2], blf[4][2];
            #pragma unroll
            for (int ni = 0; ni < 4; ni++) {
                const int nr = (wn << 5) + (ni << 3) + bg;
                bhf[ni][0] = *(const uint32_t*)&Bh[nr][ks + bc];
                bhf[ni][1] = *(const uint32_t*)&Bh[nr][ks + bc + 8];
                blf[ni][0] = *(const uint32_t*)&Bl[nr][ks + bc];
                blf[ni][1] = *(const uint32_t*)&Bl[nr][ks + bc + 8];
            }
            #pragma unroll
            for (int mi = 0; mi < 4; mi++) {
                const int ar = (wm << 6) + (mi << 4) + bg;
                uint32_t ahf[4], alf[4];
                ahf[0] = *(const uint32_t*)&Ah[ar][ks + bc];
                ahf[1] = *(const uint32_t*)&Ah[ar + 8][ks + bc];
                ahf[2] = *(const uint32_t*)&Ah[ar][ks + bc + 8];
                ahf[3] = *(const uint32_t*)&Ah[ar + 8][ks + bc + 8];
                alf[0] = *(const uint32_t*)&Al[ar][ks + bc];
                alf[1] = *(const uint32_t*)&Al[ar + 8][ks + bc];
                alf[2] = *(const uint32_t*)&Al[ar][ks + bc + 8];
                alf[3] = *(const uint32_t*)&Al[ar + 8][ks + bc + 8];
                #pragma unroll
                for (int ni = 0; ni < 4; ni++) {
                    mma_bf16(acc[mi][ni], ahf, bhf[ni]);
                    mma_bf16(acc[mi][ni], ahf, blf[ni]);
                    mma_bf16(acc[mi][ni], alf, bhf[ni]);
                }
            }
        }
    }

    // Epilogue: per-warp 64x32 tile; each lane owns rows {g, g+8}, 2 cols
    #pragma unroll
    for (int mi = 0; mi < 4; mi++) {
        const int r0 = m0 + (wm << 6) + (mi << 4) + bg;
        #pragma unroll
        for (int ni = 0; ni < 4; ni++) {
            const int c = n0 + (wn << 5) + (ni << 3) + bc;
            float2 v0 = make_float2(acc[mi][ni][0], acc[mi][ni][1]);
            float2 v1 = make_float2(acc[mi][ni][2], acc[mi][ni][3]);
            if (bias) {
                const float2 bb = *(const float2*)&bias[c];
                v0.x += bb.x; v0.y += bb.y;
                v1.x += bb.x; v1.y += bb.y;
            }
            *(float2*)&C[(size_t)r0 * Nc + c] = v0;
            *(float2*)&C[(size_t)(r0 + 8) * Nc + c] = v1;
        }
    }
}

// ---------------------------------------------------------------------------
// Flash attention (fp32, f32x2-packed inner loops)
// ---------------------------------------------------------------------------
#define LDSN 68
#define FLASH_SMEM_FLOATS (4 * 64 * LDSN + 3 * 64)
#define FLASH_SMEM_BYTES  (FLASH_SMEM_FLOATS * 4)

__global__ void __launch_bounds__(256) flash_attn_kernel(
    const float* __restrict__ qkv, const void* __restrict__ maskp,
    float* __restrict__ ctx)
{
    extern __shared__ float sm[];
    float* Qs  = sm;
    float* Ks  = Qs + 64 * LDSN;
    float* Vs  = Ks + 64 * LDSN;
    float* Ss  = Vs + 64 * LDSN;
    float* m_s = Ss + 64 * LDSN;
    float* l_s = m_s + 64;
    float* a_s = l_s + 64;

    const int tid = threadIdx.x;
    const int tx = tid & 15, ty = tid >> 4;
    const int bn = blockIdx.y;
    const int b = bn >> 4, n = bn & 15;
    const int f0 = blockIdx.x << 6;
    const int maskIsInt = g_mask_is_int;
    const float scale = 0.125f;

    const int lr = tid >> 2;
    const int lc = (tid & 3) << 4;

    { // Q tile [64 f x 64 e]
        const float* src = qkv + (size_t)((f0 + lr) * BD + b) * D3 + n * 192;
        #pragma unroll
        for (int c = 0; c < 16; c += 4)
            *(float4*)&Qs[lr * LDSN + lc + c] = *(const float4*)&src[lc + c];
    }
    if (tid < 64) { m_s[tid] = -1e30f; l_s[tid] = 0.f; }

    u64 acc2[4][2] = {};   // packed fp32 pairs over output e-columns

    for (int t0 = 0; t0 < FD; t0 += 64) {
        __syncthreads();
        {
            const float* srcK = qkv + (size_t)((t0 + lr) * BD + b) * D3 + n * 192 + 64;
            const float* srcV = srcK + 64;
            #pragma unroll
            for (int c = 0; c < 16; c += 4) {
                *(float4*)&Ks[lr * LDSN + lc + c] = *(const float4*)&srcK[lc + c];
                *(float4*)&Vs[lr * LDSN + lc + c] = *(const float4*)&srcV[lc + c];
            }
        }
        __syncthreads();

        // S = Q K^T via packed FFMA2 over e-pairs
        u64 s2[4][4];
        #pragma unroll
        for (int i = 0; i < 4; i++)
            #pragma unroll
            for (int j = 0; j < 4; j++) s2[i][j] = 0ULL;
        #pragma unroll
        for (int e = 0; e < 64; e += 4) {
            float4 q[4], k[4];
            #pragma unroll
            for (int i = 0; i < 4; i++) q[i] = *(const float4*)&Qs[(ty*4+i)*LDSN + e];
            #pragma unroll
            for (int j = 0; j < 4; j++) k[j] = *(const float4*)&Ks[(tx*4+j)*LDSN + e];
            #pragma unroll
            for (int i = 0; i < 4; i++) {
                const u64* qp = reinterpret_cast<const u64*>(&q[i]);
                #pragma unroll
                for (int j = 0; j < 4; j++) {
                    const u64* kp = reinterpret_cast<const u64*>(&k[j]);
                    s2[i][j] = fma2(qp[0], kp[0], s2[i][j]);
                    s2[i][j] = fma2(qp[1], kp[1], s2[i][j]);
                }
            }
        }
        float s[4][4];
        #pragma unroll
        for (int i = 0; i < 4; i++)
            #pragma unroll
            for (int j = 0; j < 4; j++) {
                float a, bb2; unpack2(s2[i][j], a, bb2);
                s[i][j] = a + bb2;
            }

        // mask + scale -> Ss
        #pragma unroll
        for (int i = 0; i < 4; i++) {
            const int fi = f0 + ty*4 + i;
            const size_t mrow = ((size_t)b * FD + fi) * FD + t0 + tx*4;
            float v0, v1, v2, v3;
            if (maskIsInt) {
                const int4 mi = *(const int4*)((const int*)maskp + mrow);
                v0 = mi.x ? s[i][0]*scale : -10000.f;
                v1 = mi.y ? s[i][1]*scale : -10000.f;
                v2 = mi.z ? s[i][2]*scale : -10000.f;
                v3 = mi.w ? s[i][3]*scale : -10000.f;
            } else {
                const uchar4 mi = *(const uchar4*)((const unsigned char*)maskp + mrow);
                v0 = mi.x ? s[i][0]*scale : -10000.f;
                v1 = mi.y ? s[i][1]*scale : -10000.f;
                v2 = mi.z ? s[i][2]*scale : -10000.f;
                v3 = mi.w ? s[i][3]*scale : -10000.f;
            }
            *(float4*)&Ss[(ty*4+i)*LDSN + tx*4] = make_float4(v0, v1, v2, v3);
        }
        __syncthreads();

        // online softmax over the 64-wide tile (4 threads per row)
        {
            const int row = tid >> 2;
            const int seg = (tid & 3) << 4;
            float mx = -1e30f;
            #pragma unroll
            for (int j = 0; j < 16; j++) mx = fmaxf(mx, Ss[row*LDSN + seg + j]);
            mx = fmaxf(mx, __shfl_xor_sync(0xffffffffu, mx, 1));
            mx = fmaxf(mx, __shfl_xor_sync(0xffffffffu, mx, 2));
            const float m_old = m_s[row];
            const float m_new = fmaxf(m_old, mx);
            float sum = 0.f;
            #pragma unroll
            for (int j = 0; j < 16; j++) {
                const float p = __expf(Ss[row*LDSN + seg + j] - m_new);
                Ss[row*LDSN + seg + j] = p;
                sum += p;
            }
            sum += __shfl_xor_sync(0xffffffffu, sum, 1);
            sum += __shfl_xor_sync(0xffffffffu, sum, 2);
            if ((tid & 3) == 0) {
                const float alpha = __expf(m_old - m_new);
                a_s[row] = alpha;
                l_s[row] = l_s[row] * alpha + sum;
                m_s[row] = m_new;
            }
        }
        __syncthreads();

        // acc = acc*alpha + P @ V  (packed over e-column pairs)
        #pragma unroll
        for (int i = 0; i < 4; i++) {
            const u64 ab = pack2(a_s[ty*4+i], a_s[ty*4+i]);
            acc2[i][0] = mul2(acc2[i][0], ab);
            acc2[i][1] = mul2(acc2[i][1], ab);
        }
        #pragma unroll
        for (int t = 0; t < 64; t += 4) {
            float4 p[4], v[4];
            #pragma unroll
            for (int i = 0; i < 4; i++) p[i] = *(const float4*)&Ss[(ty*4+i)*LDSN + t];
            #pragma unroll
            for (int k = 0; k < 4; k++) v[k] = *(const float4*)&Vs[(t+k)*LDSN + tx*4];
            #pragma unroll
            for (int i = 0; i < 4; i++) {
                const float* pf = reinterpret_cast<const float*>(&p[i]);
                #pragma unroll
                for (int k = 0; k < 4; k++) {
                    const u64 pb = pack2(pf[k], pf[k]);
                    const u64* vp = reinterpret_cast<const u64*>(&v[k]);
                    acc2[i][0] = fma2(pb, vp[0], acc2[i][0]);
                    acc2[i][1] = fma2(pb, vp[1], acc2[i][1]);
                }
            }
        }
    }

    // normalize + store ctx[f,b, n*64+e]
    #pragma unroll
    for (int i = 0; i < 4; i++) {
        const float inv = 1.0f / l_s[ty*4+i];
        const int fi = f0 + ty*4 + i;
        float o0, o1, o2, o3;
        unpack2(acc2[i][0], o0, o1);
        unpack2(acc2[i][1], o2, o3);
        float4 o = make_float4(o0*inv, o1*inv, o2*inv, o3*inv);
        *(float4*)&ctx[(size_t)(fi * BD + b) * HD + n * 64 + tx*4] = o;
    }
}

// ---------------------------------------------------------------------------
__global__ void copy_tail_kernel(const float* __restrict__ src,
                                 float* __restrict__ dst, int count) {
    const int i = blockIdx.x * blockDim.x + threadIdx.x;
    if (i < count) dst[i] = src[i];
}

// ---------------------------------------------------------------------------
extern "C" void kernel_launch(void* const* d_in, const int* in_sizes, int n_in,
                              void* d_out, int out_size)
{
    const float* q_input = (const float*)d_in[0];
    const void*  mask    = d_in[1];
    const float* w_qkv   = (const float*)d_in[2];
    const float* b_qkv   = (const float*)d_in[3];
    const float* w_out   = (const float*)d_in[4];
    const float* b_out   = (const float*)d_in[5];
    float* out = (float*)d_out;

    float *qkv = nullptr, *ctx = nullptr;
    __nv_bfloat16 *wqh, *wql, *woh, *wol;
    cudaGetSymbolAddress((void**)&qkv, g_qkv);
    cudaGetSymbolAddress((void**)&ctx, g_ctx);
    cudaGetSymbolAddress((void**)&wqh, g_wqkvT_hi);
    cudaGetSymbolAddress((void**)&wql, g_wqkvT_lo);
    cudaGetSymbolAddress((void**)&woh, g_woutT_hi);
    cudaGetSymbolAddress((void**)&wol, g_woutT_lo);

    // 0) mask dtype probe
    detect_mask_kernel<<<1, 256>>>((const unsigned char*)mask);

    // 0b) transpose+split weights: W[K,Nc] -> W^T[Nc,K] bf16 hi/lo
    transpose_split_kernel<<<dim3(D3 / 32, HD / 32), 256>>>(w_qkv, wqh, wql, HD, D3);
    transpose_split_kernel<<<dim3(HD / 32, HD / 32), 256>>>(w_out, woh, wol, HD, HD);

    // 1) QKV projection on tensor cores: [4096,1024] x [1024,3072] + bias
    {
        dim3 grid(D3 / 128, MROWS / 128);
        mma_gemm_kernel<<<grid, 256>>>(q_input, wqh, wql, b_qkv, qkv,
                                       MROWS, D3, HD);
    }

    // 2) flash attention per (f-tile, b*n)
    {
        cudaFuncSetAttribute(flash_attn_kernel,
                             cudaFuncAttributeMaxDynamicSharedMemorySize,
                             FLASH_SMEM_BYTES);
        dim3 grid(FD / 64, BD * NH);
        flash_attn_kernel<<<grid, 256, FLASH_SMEM_BYTES>>>(qkv, mask, ctx);
    }

    // 3) output projection on tensor cores: [4096,1024] x [1024,1024] -> d_out
    {
        dim3 grid(HD / 128, MROWS / 128);
        mma_gemm_kernel<<<grid, 256>>>(ctx, woh, wol, nullptr, out,
                                       MROWS, HD, HD);
    }

    // 4) tuple tail: b_out appended after the [F,B,H] output
    const int main_elems = MROWS * HD;
    const int tail = out_size - main_elems;
    if (tail > 0) {
        copy_tail_kernel<<<(tail + 255) / 256, 256>>>(b_out, out + main_elems, tail);
    }
}

// round 11
// speedup vs baseline: 1.9328x; 1.5805x over previous
#include <cuda_runtime.h>
#include <cuda_bf16.h>
#include <cstdint>

// Problem dims (fixed by the reference)
#define FD 2048
#define BD 2
#define HD 1024
#define NH 16
#define ED 64
#define D3 3072          // 3*HD
#define MROWS 4096       // FD*BD

// ---------------------------------------------------------------------------
// Scratch (static device globals — no allocations allowed)
// ---------------------------------------------------------------------------
__device__ float g_qkv[(size_t)MROWS * D3];   // [f*B+b, 3H] fp32
__device__ float g_ctx[(size_t)MROWS * HD];   // [f*B+b, n*64+e] fp32
__device__ __nv_bfloat16 g_wqkvT_hi[(size_t)D3 * HD];  // W^T [3072,1024]
__device__ __nv_bfloat16 g_wqkvT_lo[(size_t)D3 * HD];
__device__ __nv_bfloat16 g_woutT_hi[(size_t)HD * HD];  // W^T [1024,1024]
__device__ __nv_bfloat16 g_woutT_lo[(size_t)HD * HD];
__device__ int g_mask_is_int;

__device__ __forceinline__ uint32_t pbf2(__nv_bfloat16 a, __nv_bfloat16 b) {
    __nv_bfloat162 t = __halves2bfloat162(a, b);
    return *reinterpret_cast<uint32_t*>(&t);
}

// m16n8k16 bf16 MMA, fp32 accumulate (HMMA path — no arch-suffix gating)
__device__ __forceinline__ void mma_bf16(float* d, const uint32_t* a,
                                         const uint32_t* b) {
    asm volatile(
        "mma.sync.aligned.m16n8k16.row.col.f32.bf16.bf16.f32 "
        "{%0,%1,%2,%3}, {%4,%5,%6,%7}, {%8,%9}, {%0,%1,%2,%3};"
        : "+f"(d[0]), "+f"(d[1]), "+f"(d[2]), "+f"(d[3])
        : "r"(a[0]), "r"(a[1]), "r"(a[2]), "r"(a[3]), "r"(b[0]), "r"(b[1]));
}

// ---------------------------------------------------------------------------
// Mask dtype detector: bool->uint8 vs bool->int32
// ---------------------------------------------------------------------------
__global__ void detect_mask_kernel(const unsigned char* __restrict__ m) {
    __shared__ int cnt;
    if (threadIdx.x == 0) cnt = 0;
    __syncthreads();
    int local = 0;
    for (int i = threadIdx.x; i < 65536; i += blockDim.x)
        if ((i & 3) && m[i]) local++;
    if (local) atomicAdd(&cnt, local);
    __syncthreads();
    if (threadIdx.x == 0) g_mask_is_int = (cnt == 0) ? 1 : 0;
}

// ---------------------------------------------------------------------------
// Transpose + hi/lo bf16 split:  W[K,Nc] fp32 -> Th/Tl[Nc,K] bf16
// ---------------------------------------------------------------------------
__global__ void __launch_bounds__(256) transpose_split_kernel(
    const float* __restrict__ W, __nv_bfloat16* __restrict__ Th,
    __nv_bfloat16* __restrict__ Tl, int K, int Nc)
{
    __shared__ float tile[32][33];
    const int tx = threadIdx.x & 31, ty = threadIdx.x >> 5;  // ty 0..7
    const int n0 = blockIdx.x * 32, k0 = blockIdx.y * 32;
    #pragma unroll
    for (int j = 0; j < 32; j += 8)
        tile[ty + j][tx] = W[(size_t)(k0 + ty + j) * Nc + n0 + tx];
    __syncthreads();
    #pragma unroll
    for (int j = 0; j < 32; j += 8) {
        float v = tile[tx][ty + j];
        __nv_bfloat16 h = __float2bfloat16(v);
        __nv_bfloat16 l = __float2bfloat16(v - __bfloat162float(h));
        size_t o = (size_t)(n0 + ty + j) * K + k0 + tx;
        Th[o] = h;
        Tl[o] = l;
    }
}

// ---------------------------------------------------------------------------
// mma.sync GEMM: C[M,Nc] = A[M,K](fp32, split inline) * BT[Nc,K]^T (bf16 hi/lo)
// CTA 128x128, BK=32, 8 warps of 64x32. 3-term bf16-split accumulation.
// ---------------------------------------------------------------------------
#define ASTR 40

__global__ void __launch_bounds__(256) mma_gemm_kernel(
    const float* __restrict__ A,
    const __nv_bfloat16* __restrict__ BTh,
    const __nv_bfloat16* __restrict__ BTl,
    const float* __restrict__ bias,
    float* __restrict__ C, int M, int Nc, int K)
{
    __shared__ __nv_bfloat16 Ah[128][ASTR], Al[128][ASTR];
    __shared__ __nv_bfloat16 Bh[128][ASTR], Bl[128][ASTR];

    const int tid = threadIdx.x, wid = tid >> 5, lane = tid & 31;
    const int wm = wid & 1, wn = wid >> 1;           // warp tile: 64(M) x 32(N)
    const int m0 = blockIdx.y << 7, n0 = blockIdx.x << 7;
    const int bg = lane >> 2, bc = (lane & 3) << 1;  // fragment lane mapping

    const int lr = tid >> 1;
    const int lh = (tid & 1) << 4;
    const float* Ap = A + (size_t)(m0 + lr) * K + lh;
    const __nv_bfloat16* Bhp = BTh + (size_t)(n0 + lr) * K + lh;
    const __nv_bfloat16* Blp = BTl + (size_t)(n0 + lr) * K + lh;

    float acc[4][4][4] = {};   // [mi][ni][c]

    for (int k0 = 0; k0 < K; k0 += 32) {
        __syncthreads();
        #pragma unroll
        for (int i = 0; i < 4; i++) {
            float4 x = *(const float4*)(Ap + k0 + (i << 2));
            __nv_bfloat16 h0 = __float2bfloat16(x.x), h1 = __float2bfloat16(x.y);
            __nv_bfloat16 h2 = __float2bfloat16(x.z), h3 = __float2bfloat16(x.w);
            __nv_bfloat16 l0 = __float2bfloat16(x.x - __bfloat162float(h0));
            __nv_bfloat16 l1 = __float2bfloat16(x.y - __bfloat162float(h1));
            __nv_bfloat16 l2 = __float2bfloat16(x.z - __bfloat162float(h2));
            __nv_bfloat16 l3 = __float2bfloat16(x.w - __bfloat162float(h3));
            *(uint2*)&Ah[lr][lh + (i << 2)] = make_uint2(pbf2(h0, h1), pbf2(h2, h3));
            *(uint2*)&Al[lr][lh + (i << 2)] = make_uint2(pbf2(l0, l1), pbf2(l2, l3));
        }
        *(uint4*)&Bh[lr][lh] = *(const uint4*)(Bhp + k0);
        *(uint4*)&Bh[lr][lh + 8] = *(const uint4*)(Bhp + k0 + 8);
        *(uint4*)&Bl[lr][lh] = *(const uint4*)(Blp + k0);
        *(uint4*)&Bl[lr][lh + 8] = *(const uint4*)(Blp + k0 + 8);
        __syncthreads();

        #pragma unroll
        for (int ks = 0; ks < 32; ks += 16) {
            uint32_t bhf[4][2], blf[4][2];
            #pragma unroll
            for (int ni = 0; ni < 4; ni++) {
                const int nr = (wn << 5) + (ni << 3) + bg;
                bhf[ni][0] = *(const uint32_t*)&Bh[nr][ks + bc];
                bhf[ni][1] = *(const uint32_t*)&Bh[nr][ks + bc + 8];
                blf[ni][0] = *(const uint32_t*)&Bl[nr][ks + bc];
                blf[ni][1] = *(const uint32_t*)&Bl[nr][ks + bc + 8];
            }
            #pragma unroll
            for (int mi = 0; mi < 4; mi++) {
                const int ar = (wm << 6) + (mi << 4) + bg;
                uint32_t ahf[4], alf[4];
                ahf[0] = *(const uint32_t*)&Ah[ar][ks + bc];
                ahf[1] = *(const uint32_t*)&Ah[ar + 8][ks + bc];
                ahf[2] = *(const uint32_t*)&Ah[ar][ks + bc + 8];
                ahf[3] = *(const uint32_t*)&Ah[ar + 8][ks + bc + 8];
                alf[0] = *(const uint32_t*)&Al[ar][ks + bc];
                alf[1] = *(const uint32_t*)&Al[ar + 8][ks + bc];
                alf[2] = *(const uint32_t*)&Al[ar][ks + bc + 8];
                alf[3] = *(const uint32_t*)&Al[ar + 8][ks + bc + 8];
                #pragma unroll
                for (int ni = 0; ni < 4; ni++) {
                    mma_bf16(acc[mi][ni], ahf, bhf[ni]);
                    mma_bf16(acc[mi][ni], ahf, blf[ni]);
                    mma_bf16(acc[mi][ni], alf, bhf[ni]);
                }
            }
        }
    }

    #pragma unroll
    for (int mi = 0; mi < 4; mi++) {
        const int r0 = m0 + (wm << 6) + (mi << 4) + bg;
        #pragma unroll
        for (int ni = 0; ni < 4; ni++) {
            const int c = n0 + (wn << 5) + (ni << 3) + bc;
            float2 v0 = make_float2(acc[mi][ni][0], acc[mi][ni][1]);
            float2 v1 = make_float2(acc[mi][ni][2], acc[mi][ni][3]);
            if (bias) {
                const float2 bb = *(const float2*)&bias[c];
                v0.x += bb.x; v0.y += bb.y;
                v1.x += bb.x; v1.y += bb.y;
            }
            *(float2*)&C[(size_t)r0 * Nc + c] = v0;
            *(float2*)&C[(size_t)(r0 + 8) * Nc + c] = v1;
        }
    }
}

// ---------------------------------------------------------------------------
// Flash attention on tensor cores (mma.sync bf16 hi/lo split).
// One block per (64-row f-tile, b*n). 8 warps: 4(M:16 rows) x 2(N:32 cols).
// BSTR = 72 (64-wide tiles + 8 pad).  Bank check: stride = 144B = 36 banks;
// fragment-load bank = (g*36 + lane&3) mod 32 = g*4 + (lane&3): conflict-free.
// ---------------------------------------------------------------------------
#define BSTR 72
#define SSTR 68
#define FTILE_B (64 * BSTR * 2)
// smem byte offsets
#define FO_QH 0
#define FO_QL (FO_QH + FTILE_B)
#define FO_KH (FO_QL + FTILE_B)
#define FO_KL (FO_KH + FTILE_B)
#define FO_VH (FO_KL + FTILE_B)
#define FO_VL (FO_VH + FTILE_B)
#define FO_PH (FO_VL + FTILE_B)
#define FO_PL (FO_PH + FTILE_B)
#define FO_SS (FO_PL + FTILE_B)
#define FO_MS (FO_SS + 64 * SSTR * 4)
#define FO_LS (FO_MS + 64 * 4)
#define FO_AS (FO_LS + 64 * 4)
#define FLASH_SMEM_BYTES (FO_AS + 64 * 4)

__global__ void __launch_bounds__(256) flash_attn_mma_kernel(
    const float* __restrict__ qkv, const void* __restrict__ maskp,
    float* __restrict__ ctx)
{
    extern __shared__ char smb[];
    __nv_bfloat16* Qh = (__nv_bfloat16*)(smb + FO_QH);
    __nv_bfloat16* Ql = (__nv_bfloat16*)(smb + FO_QL);
    __nv_bfloat16* Kh = (__nv_bfloat16*)(smb + FO_KH);
    __nv_bfloat16* Kl = (__nv_bfloat16*)(smb + FO_KL);
    __nv_bfloat16* Vh = (__nv_bfloat16*)(smb + FO_VH);   // [e][t] (transposed)
    __nv_bfloat16* Vl = (__nv_bfloat16*)(smb + FO_VL);
    __nv_bfloat16* Ph = (__nv_bfloat16*)(smb + FO_PH);
    __nv_bfloat16* Pl = (__nv_bfloat16*)(smb + FO_PL);
    float* Ss  = (float*)(smb + FO_SS);
    float* m_s = (float*)(smb + FO_MS);
    float* l_s = (float*)(smb + FO_LS);
    float* a_s = (float*)(smb + FO_AS);

    const int tid = threadIdx.x, wid = tid >> 5, lane = tid & 31;
    const int wm = wid & 3, wnw = wid >> 2;
    const int g = lane >> 2, bc = (lane & 3) << 1;
    const int bn = blockIdx.y;
    const int b = bn >> 4, n = bn & 15;
    const int f0 = blockIdx.x << 6;
    const int maskIsInt = g_mask_is_int;
    const float scale = 0.125f;

    // loader mapping: 4 threads per row, 16 floats each
    const int lr = tid >> 2;
    const int lc = (tid & 3) << 4;
    const int erot = lc >> 4;       // stagger for transposed V store

    { // Q tile: fp32 -> hi/lo bf16
        const float* src = qkv + (size_t)((f0 + lr) * BD + b) * D3 + n * 192;
        #pragma unroll
        for (int c = 0; c < 16; c += 4) {
            float4 x = *(const float4*)&src[lc + c];
            __nv_bfloat16 h0 = __float2bfloat16(x.x), h1 = __float2bfloat16(x.y);
            __nv_bfloat16 h2 = __float2bfloat16(x.z), h3 = __float2bfloat16(x.w);
            __nv_bfloat16 l0 = __float2bfloat16(x.x - __bfloat162float(h0));
            __nv_bfloat16 l1 = __float2bfloat16(x.y - __bfloat162float(h1));
            __nv_bfloat16 l2 = __float2bfloat16(x.z - __bfloat162float(h2));
            __nv_bfloat16 l3 = __float2bfloat16(x.w - __bfloat162float(h3));
            *(uint2*)&Qh[lr * BSTR + lc + c] = make_uint2(pbf2(h0, h1), pbf2(h2, h3));
            *(uint2*)&Ql[lr * BSTR + lc + c] = make_uint2(pbf2(l0, l1), pbf2(l2, l3));
        }
    }
    if (tid < 64) { m_s[tid] = -1e30f; l_s[tid] = 0.f; }

    const int r0 = wm * 16 + g;     // this lane's first output row (local)
    float oacc[4][4] = {};

    for (int t0 = 0; t0 < FD; t0 += 64) {
        __syncthreads();   // prior-iteration PV done; safe to overwrite K/V

        { // K tile -> Kh/Kl [t][e]; V tile -> Vh/Vl [e][t] (transposed)
            const float* srcK = qkv + (size_t)((t0 + lr) * BD + b) * D3 + n * 192 + 64;
            const float* srcV = srcK + 64;
            float vv[16];
            #pragma unroll
            for (int c = 0; c < 16; c += 4) {
                float4 x = *(const float4*)&srcK[lc + c];
                __nv_bfloat16 h0 = __float2bfloat16(x.x), h1 = __float2bfloat16(x.y);
                __nv_bfloat16 h2 = __float2bfloat16(x.z), h3 = __float2bfloat16(x.w);
                __nv_bfloat16 l0 = __float2bfloat16(x.x - __bfloat162float(h0));
                __nv_bfloat16 l1 = __float2bfloat16(x.y - __bfloat162float(h1));
                __nv_bfloat16 l2 = __float2bfloat16(x.z - __bfloat162float(h2));
                __nv_bfloat16 l3 = __float2bfloat16(x.w - __bfloat162float(h3));
                *(uint2*)&Kh[lr * BSTR + lc + c] = make_uint2(pbf2(h0, h1), pbf2(h2, h3));
                *(uint2*)&Kl[lr * BSTR + lc + c] = make_uint2(pbf2(l0, l1), pbf2(l2, l3));
                float4 y = *(const float4*)&srcV[lc + c];
                vv[c] = y.x; vv[c + 1] = y.y; vv[c + 2] = y.z; vv[c + 3] = y.w;
            }
            #pragma unroll
            for (int jj = 0; jj < 16; jj++) {
                const int j = (jj + erot) & 15;
                const float v = vv[j];
                __nv_bfloat16 h = __float2bfloat16(v);
                __nv_bfloat16 l = __float2bfloat16(v - __bfloat162float(h));
                Vh[(lc + j) * BSTR + lr] = h;
                Vl[(lc + j) * BSTR + lr] = l;
            }
        }
        __syncthreads();

        // ---- S = Q K^T (3-term bf16 split) ----
        float sacc[4][4] = {};
        #pragma unroll
        for (int ks = 0; ks < 64; ks += 16) {
            uint32_t ahf[4], alf[4];
            ahf[0] = *(const uint32_t*)&Qh[r0 * BSTR + ks + bc];
            ahf[1] = *(const uint32_t*)&Qh[(r0 + 8) * BSTR + ks + bc];
            ahf[2] = *(const uint32_t*)&Qh[r0 * BSTR + ks + bc + 8];
            ahf[3] = *(const uint32_t*)&Qh[(r0 + 8) * BSTR + ks + bc + 8];
            alf[0] = *(const uint32_t*)&Ql[r0 * BSTR + ks + bc];
            alf[1] = *(const uint32_t*)&Ql[(r0 + 8) * BSTR + ks + bc];
            alf[2] = *(const uint32_t*)&Ql[r0 * BSTR + ks + bc + 8];
            alf[3] = *(const uint32_t*)&Ql[(r0 + 8) * BSTR + ks + bc + 8];
            #pragma unroll
            for (int ni = 0; ni < 4; ni++) {
                const int nr = wnw * 32 + ni * 8 + g;
                uint32_t bhf[2], blf[2];
                bhf[0] = *(const uint32_t*)&Kh[nr * BSTR + ks + bc];
                bhf[1] = *(const uint32_t*)&Kh[nr * BSTR + ks + bc + 8];
                blf[0] = *(const uint32_t*)&Kl[nr * BSTR + ks + bc];
                blf[1] = *(const uint32_t*)&Kl[nr * BSTR + ks + bc + 8];
                mma_bf16(sacc[ni], ahf, bhf);
                mma_bf16(sacc[ni], ahf, blf);
                mma_bf16(sacc[ni], alf, bhf);
            }
        }

        // ---- mask + scale -> Ss ----
        #pragma unroll
        for (int ni = 0; ni < 4; ni++) {
            const int col = wnw * 32 + ni * 8 + bc;
            const size_t mb0 = ((size_t)b * FD + f0 + r0) * FD + t0 + col;
            const size_t mb1 = mb0 + (size_t)8 * FD;
            float v0, v1, v2, v3;
            if (maskIsInt) {
                const int2 m0i = *(const int2*)((const int*)maskp + mb0);
                const int2 m1i = *(const int2*)((const int*)maskp + mb1);
                v0 = m0i.x ? sacc[ni][0] * scale : -10000.f;
                v1 = m0i.y ? sacc[ni][1] * scale : -10000.f;
                v2 = m1i.x ? sacc[ni][2] * scale : -10000.f;
                v3 = m1i.y ? sacc[ni][3] * scale : -10000.f;
            } else {
                const uchar2 m0c = *(const uchar2*)((const unsigned char*)maskp + mb0);
                const uchar2 m1c = *(const uchar2*)((const unsigned char*)maskp + mb1);
                v0 = m0c.x ? sacc[ni][0] * scale : -10000.f;
                v1 = m0c.y ? sacc[ni][1] * scale : -10000.f;
                v2 = m1c.x ? sacc[ni][2] * scale : -10000.f;
                v3 = m1c.y ? sacc[ni][3] * scale : -10000.f;
            }
            *(float2*)&Ss[r0 * SSTR + col] = make_float2(v0, v1);
            *(float2*)&Ss[(r0 + 8) * SSTR + col] = make_float2(v2, v3);
        }
        __syncthreads();

        // ---- online softmax; emit P as bf16 hi/lo ----
        {
            const int row = tid >> 2;
            const int seg = (tid & 3) << 4;
            float mx = -1e30f;
            #pragma unroll
            for (int j = 0; j < 16; j++) mx = fmaxf(mx, Ss[row * SSTR + seg + j]);
            mx = fmaxf(mx, __shfl_xor_sync(0xffffffffu, mx, 1));
            mx = fmaxf(mx, __shfl_xor_sync(0xffffffffu, mx, 2));
            const float m_old = m_s[row];
            const float m_new = fmaxf(m_old, mx);
            float sum = 0.f;
            #pragma unroll
            for (int j = 0; j < 16; j++) {
                const float p = __expf(Ss[row * SSTR + seg + j] - m_new);
                sum += p;
                const __nv_bfloat16 h = __float2bfloat16(p);
                const __nv_bfloat16 l = __float2bfloat16(p - __bfloat162float(h));
                Ph[row * BSTR + seg + j] = h;
                Pl[row * BSTR + seg + j] = l;
            }
            sum += __shfl_xor_sync(0xffffffffu, sum, 1);
            sum += __shfl_xor_sync(0xffffffffu, sum, 2);
            if ((tid & 3) == 0) {
                const float alpha = __expf(m_old - m_new);
                a_s[row] = alpha;
                l_s[row] = l_s[row] * alpha + sum;
                m_s[row] = m_new;
            }
        }
        __syncthreads();

        // ---- oacc = oacc*alpha + P V (3-term bf16 split) ----
        {
            const float a0 = a_s[r0], a1 = a_s[r0 + 8];
            #pragma unroll
            for (int ni = 0; ni < 4; ni++) {
                oacc[ni][0] *= a0; oacc[ni][1] *= a0;
                oacc[ni][2] *= a1; oacc[ni][3] *= a1;
            }
        }
        #pragma unroll
        for (int ks = 0; ks < 64; ks += 16) {
            uint32_t ahf[4], alf[4];
            ahf[0] = *(const uint32_t*)&Ph[r0 * BSTR + ks + bc];
            ahf[1] = *(const uint32_t*)&Ph[(r0 + 8) * BSTR + ks + bc];
            ahf[2] = *(const uint32_t*)&Ph[r0 * BSTR + ks + bc + 8];
            ahf[3] = *(const uint32_t*)&Ph[(r0 + 8) * BSTR + ks + bc + 8];
            alf[0] = *(const uint32_t*)&Pl[r0 * BSTR + ks + bc];
            alf[1] = *(const uint32_t*)&Pl[(r0 + 8) * BSTR + ks + bc];
            alf[2] = *(const uint32_t*)&Pl[r0 * BSTR + ks + bc + 8];
            alf[3] = *(const uint32_t*)&Pl[(r0 + 8) * BSTR + ks + bc + 8];
            #pragma unroll
            for (int ni = 0; ni < 4; ni++) {
                const int nr = wnw * 32 + ni * 8 + g;   // e-row of V^T
                uint32_t bhf[2], blf[2];
                bhf[0] = *(const uint32_t*)&Vh[nr * BSTR + ks + bc];
                bhf[1] = *(const uint32_t*)&Vh[nr * BSTR + ks + bc + 8];
                blf[0] = *(const uint32_t*)&Vl[nr * BSTR + ks + bc];
                blf[1] = *(const uint32_t*)&Vl[nr * BSTR + ks + bc + 8];
                mma_bf16(oacc[ni], ahf, bhf);
                mma_bf16(oacc[ni], ahf, blf);
                mma_bf16(oacc[ni], alf, bhf);
            }
        }
    }

    // normalize + store ctx[f,b, n*64+e]
    {
        const float inv0 = 1.0f / l_s[r0];
        const float inv1 = 1.0f / l_s[r0 + 8];
        #pragma unroll
        for (int ni = 0; ni < 4; ni++) {
            const int e = wnw * 32 + ni * 8 + bc;
            const size_t o0 = (size_t)((f0 + r0) * BD + b) * HD + n * 64 + e;
            const size_t o1 = (size_t)((f0 + r0 + 8) * BD + b) * HD + n * 64 + e;
            *(float2*)&ctx[o0] = make_float2(oacc[ni][0] * inv0, oacc[ni][1] * inv0);
            *(float2*)&ctx[o1] = make_float2(oacc[ni][2] * inv1, oacc[ni][3] * inv1);
        }
    }
}

// ---------------------------------------------------------------------------
__global__ void copy_tail_kernel(const float* __restrict__ src,
                                 float* __restrict__ dst, int count) {
    const int i = blockIdx.x * blockDim.x + threadIdx.x;
    if (i < count) dst[i] = src[i];
}

// ---------------------------------------------------------------------------
extern "C" void kernel_launch(void* const* d_in, const int* in_sizes, int n_in,
                              void* d_out, int out_size)
{
    const float* q_input = (const float*)d_in[0];
    const void*  mask    = d_in[1];
    const float* w_qkv   = (const float*)d_in[2];
    const float* b_qkv   = (const float*)d_in[3];
    const float* w_out   = (const float*)d_in[4];
    const float* b_out   = (const float*)d_in[5];
    float* out = (float*)d_out;

    float *qkv = nullptr, *ctx = nullptr;
    __nv_bfloat16 *wqh, *wql, *woh, *wol;
    cudaGetSymbolAddress((void**)&qkv, g_qkv);
    cudaGetSymbolAddress((void**)&ctx, g_ctx);
    cudaGetSymbolAddress((void**)&wqh, g_wqkvT_hi);
    cudaGetSymbolAddress((void**)&wql, g_wqkvT_lo);
    cudaGetSymbolAddress((void**)&woh, g_woutT_hi);
    cudaGetSymbolAddress((void**)&wol, g_woutT_lo);

    // 0) mask dtype probe
    detect_mask_kernel<<<1, 256>>>((const unsigned char*)mask);

    // 0b) transpose+split weights: W[K,Nc] -> W^T[Nc,K] bf16 hi/lo
    transpose_split_kernel<<<dim3(D3 / 32, HD / 32), 256>>>(w_qkv, wqh, wql, HD, D3);
    transpose_split_kernel<<<dim3(HD / 32, HD / 32), 256>>>(w_out, woh, wol, HD, HD);

    // 1) QKV projection on tensor cores
    {
        dim3 grid(D3 / 128, MROWS / 128);
        mma_gemm_kernel<<<grid, 256>>>(q_input, wqh, wql, b_qkv, qkv,
                                       MROWS, D3, HD);
    }

    // 2) flash attention on tensor cores
    {
        cudaFuncSetAttribute(flash_attn_mma_kernel,
                             cudaFuncAttributeMaxDynamicSharedMemorySize,
                             FLASH_SMEM_BYTES);
        dim3 grid(FD / 64, BD * NH);
        flash_attn_mma_kernel<<<grid, 256, FLASH_SMEM_BYTES>>>(qkv, mask, ctx);
    }

    // 3) output projection on tensor cores
    {
        dim3 grid(HD / 128, MROWS / 128);
        mma_gemm_kernel<<<grid, 256>>>(ctx, woh, wol, nullptr, out,
                                       MROWS, HD, HD);
    }

    // 4) tuple tail: b_out appended after the [F,B,H] output
    const int main_elems = MROWS * HD;
    const int tail = out_size - main_elems;
    if (tail > 0) {
        copy_tail_kernel<<<(tail + 255) / 256, 256>>>(b_out, out + main_elems, tail);
    }
}

// round 13
// speedup vs baseline: 2.2013x; 1.1389x over previous
#include <cuda_runtime.h>
#include <cuda_bf16.h>
#include <cstdint>

// Problem dims (fixed by the reference)
#define FD 2048
#define BD 2
#define HD 1024
#define NH 16
#define ED 64
#define D3 3072          // 3*HD
#define MROWS 4096       // FD*BD
#define NBN 32           // BD*NH

// ---------------------------------------------------------------------------
// Scratch (static device globals — no allocations allowed)
// ---------------------------------------------------------------------------
__device__ float g_qkv[(size_t)MROWS * D3];                // QKV GEMM output fp32
__device__ __nv_bfloat16 g_wqkvT_hi[(size_t)D3 * HD];
__device__ __nv_bfloat16 g_wqkvT_lo[(size_t)D3 * HD];
__device__ __nv_bfloat16 g_woutT_hi[(size_t)HD * HD];
__device__ __nv_bfloat16 g_woutT_lo[(size_t)HD * HD];
__device__ __nv_bfloat16 g_aq_hi[(size_t)MROWS * HD];      // q_input split
__device__ __nv_bfloat16 g_aq_lo[(size_t)MROWS * HD];
__device__ __nv_bfloat16 g_Qh[(size_t)NBN * FD * ED];      // [bn][f][e]
__device__ __nv_bfloat16 g_Ql[(size_t)NBN * FD * ED];
__device__ __nv_bfloat16 g_Kh[(size_t)NBN * FD * ED];      // [bn][t][e]
__device__ __nv_bfloat16 g_Kl[(size_t)NBN * FD * ED];
__device__ __nv_bfloat16 g_Vth[(size_t)NBN * ED * FD];     // [bn][e][t]
__device__ __nv_bfloat16 g_Vtl[(size_t)NBN * ED * FD];
__device__ __nv_bfloat16 g_ctx_hi[(size_t)MROWS * HD];     // flash out, split
__device__ __nv_bfloat16 g_ctx_lo[(size_t)MROWS * HD];
__device__ int g_mask_is_int;

__device__ __forceinline__ uint32_t pbf2(__nv_bfloat16 a, __nv_bfloat16 b) {
    __nv_bfloat162 t = __halves2bfloat162(a, b);
    return *reinterpret_cast<uint32_t*>(&t);
}

// m16n8k16 bf16 MMA, fp32 accumulate (HMMA path — no arch-suffix gating)
__device__ __forceinline__ void mma_bf16(float* d, const uint32_t* a,
                                         const uint32_t* b) {
    asm volatile(
        "mma.sync.aligned.m16n8k16.row.col.f32.bf16.bf16.f32 "
        "{%0,%1,%2,%3}, {%4,%5,%6,%7}, {%8,%9}, {%0,%1,%2,%3};"
        : "+f"(d[0]), "+f"(d[1]), "+f"(d[2]), "+f"(d[3])
        : "r"(a[0]), "r"(a[1]), "r"(a[2]), "r"(a[3]), "r"(b[0]), "r"(b[1]));
}

// ---------------------------------------------------------------------------
// Mask dtype detector: bool->uint8 vs bool->int32
// ---------------------------------------------------------------------------
__global__ void detect_mask_kernel(const unsigned char* __restrict__ m) {
    __shared__ int cnt;
    if (threadIdx.x == 0) cnt = 0;
    __syncthreads();
    int local = 0;
    for (int i = threadIdx.x; i < 65536; i += blockDim.x)
        if ((i & 3) && m[i]) local++;
    if (local) atomicAdd(&cnt, local);
    __syncthreads();
    if (threadIdx.x == 0) g_mask_is_int = (cnt == 0) ? 1 : 0;
}

// ---------------------------------------------------------------------------
// Elementwise fp32 -> hi/lo bf16 split (same layout)
// ---------------------------------------------------------------------------
__global__ void __launch_bounds__(256) split_kernel(
    const float* __restrict__ src, __nv_bfloat16* __restrict__ h,
    __nv_bfloat16* __restrict__ l, int count4)
{
    const int i = blockIdx.x * blockDim.x + threadIdx.x;
    if (i >= count4) return;
    const float4 x = ((const float4*)src)[i];
    __nv_bfloat16 h0 = __float2bfloat16(x.x), h1 = __float2bfloat16(x.y);
    __nv_bfloat16 h2 = __float2bfloat16(x.z), h3 = __float2bfloat16(x.w);
    __nv_bfloat16 l0 = __float2bfloat16(x.x - __bfloat162float(h0));
    __nv_bfloat16 l1 = __float2bfloat16(x.y - __bfloat162float(h1));
    __nv_bfloat16 l2 = __float2bfloat16(x.z - __bfloat162float(h2));
    __nv_bfloat16 l3 = __float2bfloat16(x.w - __bfloat162float(h3));
    ((uint2*)h)[i] = make_uint2(pbf2(h0, h1), pbf2(h2, h3));
    ((uint2*)l)[i] = make_uint2(pbf2(l0, l1), pbf2(l2, l3));
}

// ---------------------------------------------------------------------------
// Transpose + hi/lo bf16 split:  W[K,Nc] fp32 -> Th/Tl[Nc,K] bf16
// ---------------------------------------------------------------------------
__global__ void __launch_bounds__(256) transpose_split_kernel(
    const float* __restrict__ W, __nv_bfloat16* __restrict__ Th,
    __nv_bfloat16* __restrict__ Tl, int K, int Nc)
{
    __shared__ float tile[32][33];
    const int tx = threadIdx.x & 31, ty = threadIdx.x >> 5;
    const int n0 = blockIdx.x * 32, k0 = blockIdx.y * 32;
    #pragma unroll
    for (int j = 0; j < 32; j += 8)
        tile[ty + j][tx] = W[(size_t)(k0 + ty + j) * Nc + n0 + tx];
    __syncthreads();
    #pragma unroll
    for (int j = 0; j < 32; j += 8) {
        float v = tile[tx][ty + j];
        __nv_bfloat16 h = __float2bfloat16(v);
        __nv_bfloat16 l = __float2bfloat16(v - __bfloat162float(h));
        size_t o = (size_t)(n0 + ty + j) * K + k0 + tx;
        Th[o] = h;
        Tl[o] = l;
    }
}

// ---------------------------------------------------------------------------
// QKV postprocess: g_qkv fp32 -> per-head split arrays (V transposed).
// One block per (64-row f-tile, bn). 256 threads.
// ---------------------------------------------------------------------------
__global__ void __launch_bounds__(256) qkv_split_kernel(
    const float* __restrict__ qkv)
{
    __shared__ __nv_bfloat16 vh[64][72], vl[64][72];
    const int tid = threadIdx.x;
    const int lr = tid >> 2;
    const int lc = (tid & 3) << 4;
    const int erot = tid & 3;
    const int bn = blockIdx.y;
    const int b = bn >> 4, n = bn & 15;
    const int f0 = blockIdx.x << 6;

    const float* src = qkv + (size_t)((f0 + lr) * BD + b) * D3 + n * 192;
    const size_t qko = ((size_t)bn * FD + f0 + lr) * ED + lc;

    float vv[16];
    #pragma unroll
    for (int c = 0; c < 16; c += 4) {
        // Q
        float4 x = *(const float4*)&src[lc + c];
        __nv_bfloat16 h0 = __float2bfloat16(x.x), h1 = __float2bfloat16(x.y);
        __nv_bfloat16 h2 = __float2bfloat16(x.z), h3 = __float2bfloat16(x.w);
        __nv_bfloat16 l0 = __float2bfloat16(x.x - __bfloat162float(h0));
        __nv_bfloat16 l1 = __float2bfloat16(x.y - __bfloat162float(h1));
        __nv_bfloat16 l2 = __float2bfloat16(x.z - __bfloat162float(h2));
        __nv_bfloat16 l3 = __float2bfloat16(x.w - __bfloat162float(h3));
        *(uint2*)&g_Qh[qko + c] = make_uint2(pbf2(h0, h1), pbf2(h2, h3));
        *(uint2*)&g_Ql[qko + c] = make_uint2(pbf2(l0, l1), pbf2(l2, l3));
        // K
        x = *(const float4*)&src[64 + lc + c];
        h0 = __float2bfloat16(x.x); h1 = __float2bfloat16(x.y);
        h2 = __float2bfloat16(x.z); h3 = __float2bfloat16(x.w);
        l0 = __float2bfloat16(x.x - __bfloat162float(h0));
        l1 = __float2bfloat16(x.y - __bfloat162float(h1));
        l2 = __float2bfloat16(x.z - __bfloat162float(h2));
        l3 = __float2bfloat16(x.w - __bfloat162float(h3));
        *(uint2*)&g_Kh[qko + c] = make_uint2(pbf2(h0, h1), pbf2(h2, h3));
        *(uint2*)&g_Kl[qko + c] = make_uint2(pbf2(l0, l1), pbf2(l2, l3));
        // V (stage for transpose)
        float4 y = *(const float4*)&src[128 + lc + c];
        vv[c] = y.x; vv[c + 1] = y.y; vv[c + 2] = y.z; vv[c + 3] = y.w;
    }
    #pragma unroll
    for (int jj = 0; jj < 16; jj++) {
        const int j = (jj + (erot << 2)) & 15;
        const float v = vv[j];
        __nv_bfloat16 h = __float2bfloat16(v);
        __nv_bfloat16 l = __float2bfloat16(v - __bfloat162float(h));
        vh[lc + j][lr] = h;
        vl[lc + j][lr] = l;
    }
    __syncthreads();
    { // write transposed rows: row e, 16 t-values per thread
        const int er = tid >> 2;
        const int seg = (tid & 3) << 4;
        const size_t vo = ((size_t)bn * ED + er) * FD + f0 + seg;
        *(uint4*)&g_Vth[vo] = *(const uint4*)&vh[er][seg];
        *(uint4*)&g_Vth[vo + 8] = *(const uint4*)&vh[er][seg + 8];
        *(uint4*)&g_Vtl[vo] = *(const uint4*)&vl[er][seg];
        *(uint4*)&g_Vtl[vo + 8] = *(const uint4*)&vl[er][seg + 8];
    }
}

// ---------------------------------------------------------------------------
// mma.sync GEMM with pre-split A:  C[M,Nc] = A * BT^T (all bf16 hi/lo, 3-term)
// CTA 128x128, BK=32, 8 warps of 64x32.
// ---------------------------------------------------------------------------
#define ASTR 40

__global__ void __launch_bounds__(256) mma_gemm_kernel(
    const __nv_bfloat16* __restrict__ Ah_g,
    const __nv_bfloat16* __restrict__ Al_g,
    const __nv_bfloat16* __restrict__ BTh,
    const __nv_bfloat16* __restrict__ BTl,
    const float* __restrict__ bias,
    float* __restrict__ C, int M, int Nc, int K)
{
    __shared__ __nv_bfloat16 Ah[128][ASTR], Al[128][ASTR];
    __shared__ __nv_bfloat16 Bh[128][ASTR], Bl[128][ASTR];

    const int tid = threadIdx.x, wid = tid >> 5, lane = tid & 31;
    const int wm = wid & 1, wn = wid >> 1;
    const int m0 = blockIdx.y << 7, n0 = blockIdx.x << 7;
    const int bg = lane >> 2, bc = (lane & 3) << 1;

    const int lr = tid >> 1;
    const int lh = (tid & 1) << 4;
    const __nv_bfloat16* Ahp = Ah_g + (size_t)(m0 + lr) * K + lh;
    const __nv_bfloat16* Alp = Al_g + (size_t)(m0 + lr) * K + lh;
    const __nv_bfloat16* Bhp = BTh + (size_t)(n0 + lr) * K + lh;
    const __nv_bfloat16* Blp = BTl + (size_t)(n0 + lr) * K + lh;

    float acc[4][4][4] = {};

    for (int k0 = 0; k0 < K; k0 += 32) {
        __syncthreads();
        *(uint4*)&Ah[lr][lh] = *(const uint4*)(Ahp + k0);
        *(uint4*)&Ah[lr][lh + 8] = *(const uint4*)(Ahp + k0 + 8);
        *(uint4*)&Al[lr][lh] = *(const uint4*)(Alp + k0);
        *(uint4*)&Al[lr][lh + 8] = *(const uint4*)(Alp + k0 + 8);
        *(uint4*)&Bh[lr][lh] = *(const uint4*)(Bhp + k0);
        *(uint4*)&Bh[lr][lh + 8] = *(const uint4*)(Bhp + k0 + 8);
        *(uint4*)&Bl[lr][lh] = *(const uint4*)(Blp + k0);
        *(uint4*)&Bl[lr][lh + 8] = *(const uint4*)(Blp + k0 + 8);
        __syncthreads();

        #pragma unroll
        for (int ks = 0; ks < 32; ks += 16) {
            uint32_t bhf[4][2], blf[4][2];
            #pragma unroll
            for (int ni = 0; ni < 4; ni++) {
                const int nr = (wn << 5) + (ni << 3) + bg;
                bhf[ni][0] = *(const uint32_t*)&Bh[nr][ks + bc];
                bhf[ni][1] = *(const uint32_t*)&Bh[nr][ks + bc + 8];
                blf[ni][0] = *(const uint32_t*)&Bl[nr][ks + bc];
                blf[ni][1] = *(const uint32_t*)&Bl[nr][ks + bc + 8];
            }
            #pragma unroll
            for (int mi = 0; mi < 4; mi++) {
                const int ar = (wm << 6) + (mi << 4) + bg;
                uint32_t ahf[4], alf[4];
                ahf[0] = *(const uint32_t*)&Ah[ar][ks + bc];
                ahf[1] = *(const uint32_t*)&Ah[ar + 8][ks + bc];
                ahf[2] = *(const uint32_t*)&Ah[ar][ks + bc + 8];
                ahf[3] = *(const uint32_t*)&Ah[ar + 8][ks + bc + 8];
                alf[0] = *(const uint32_t*)&Al[ar][ks + bc];
                alf[1] = *(const uint32_t*)&Al[ar + 8][ks + bc];
                alf[2] = *(const uint32_t*)&Al[ar][ks + bc + 8];
                alf[3] = *(const uint32_t*)&Al[ar + 8][ks + bc + 8];
                #pragma unroll
                for (int ni = 0; ni < 4; ni++) {
                    mma_bf16(acc[mi][ni], ahf, bhf[ni]);
                    mma_bf16(acc[mi][ni], ahf, blf[ni]);
                    mma_bf16(acc[mi][ni], alf, bhf[ni]);
                }
            }
        }
    }

    #pragma unroll
    for (int mi = 0; mi < 4; mi++) {
        const int r0 = m0 + (wm << 6) + (mi << 4) + bg;
        #pragma unroll
        for (int ni = 0; ni < 4; ni++) {
            const int c = n0 + (wn << 5) + (ni << 3) + bc;
            float2 v0 = make_float2(acc[mi][ni][0], acc[mi][ni][1]);
            float2 v1 = make_float2(acc[mi][ni][2], acc[mi][ni][3]);
            if (bias) {
                const float2 bb = *(const float2*)&bias[c];
                v0.x += bb.x; v0.y += bb.y;
                v1.x += bb.x; v1.y += bb.y;
            }
            *(float2*)&C[(size_t)r0 * Nc + c] = v0;
            *(float2*)&C[(size_t)(r0 + 8) * Nc + c] = v1;
        }
    }
}

// ---------------------------------------------------------------------------
// Flash attention on tensor cores — all operands pre-split bf16 in gmem.
// One block per (64-row f-tile, bn). 8 warps: 4(M:16 rows) x 2(N:32 cols).
// ---------------------------------------------------------------------------
#define BSTR 72
#define SSTR 68
#define FTILE_B (64 * BSTR * 2)
#define FO_QH 0
#define FO_QL (FO_QH + FTILE_B)
#define FO_KH (FO_QL + FTILE_B)
#define FO_KL (FO_KH + FTILE_B)
#define FO_VH (FO_KL + FTILE_B)
#define FO_VL (FO_VH + FTILE_B)
#define FO_PH (FO_VL + FTILE_B)
#define FO_PL (FO_PH + FTILE_B)
#define FO_SS (FO_PL + FTILE_B)
#define FO_MS (FO_SS + 64 * SSTR * 4)
#define FO_LS (FO_MS + 64 * 4)
#define FO_AS (FO_LS + 64 * 4)
#define FLASH_SMEM_BYTES (FO_AS + 64 * 4)

__global__ void __launch_bounds__(256) flash_attn_mma_kernel(
    const void* __restrict__ maskp)
{
    extern __shared__ char smb[];
    __nv_bfloat16* sQh = (__nv_bfloat16*)(smb + FO_QH);
    __nv_bfloat16* sQl = (__nv_bfloat16*)(smb + FO_QL);
    __nv_bfloat16* sKh = (__nv_bfloat16*)(smb + FO_KH);
    __nv_bfloat16* sKl = (__nv_bfloat16*)(smb + FO_KL);
    __nv_bfloat16* sVh = (__nv_bfloat16*)(smb + FO_VH);   // [e][t]
    __nv_bfloat16* sVl = (__nv_bfloat16*)(smb + FO_VL);
    __nv_bfloat16* sPh = (__nv_bfloat16*)(smb + FO_PH);
    __nv_bfloat16* sPl = (__nv_bfloat16*)(smb + FO_PL);
    float* Ss  = (float*)(smb + FO_SS);
    float* m_s = (float*)(smb + FO_MS);
    float* l_s = (float*)(smb + FO_LS);
    float* a_s = (float*)(smb + FO_AS);

    const int tid = threadIdx.x, wid = tid >> 5, lane = tid & 31;
    const int wm = wid & 3, wnw = wid >> 2;
    const int g = lane >> 2, bc = (lane & 3) << 1;
    const int bn = blockIdx.y;
    const int b = bn >> 4, n = bn & 15;
    const int f0 = blockIdx.x << 6;
    const int maskIsInt = g_mask_is_int;
    const float scale = 0.125f;

    const int lr = tid >> 2;
    const int lc = (tid & 3) << 4;

    { // Q tile: plain bf16 copies
        const size_t qo = ((size_t)bn * FD + f0 + lr) * ED + lc;
        *(uint4*)&sQh[lr * BSTR + lc] = *(const uint4*)&g_Qh[qo];
        *(uint4*)&sQh[lr * BSTR + lc + 8] = *(const uint4*)&g_Qh[qo + 8];
        *(uint4*)&sQl[lr * BSTR + lc] = *(const uint4*)&g_Ql[qo];
        *(uint4*)&sQl[lr * BSTR + lc + 8] = *(const uint4*)&g_Ql[qo + 8];
    }
    if (tid < 64) { m_s[tid] = -1e30f; l_s[tid] = 0.f; }

    const int r0 = wm * 16 + g;
    float oacc[4][4] = {};

    for (int t0 = 0; t0 < FD; t0 += 64) {
        __syncthreads();
        { // K [t][e] rows and V^T [e][t] rows: plain bf16 copies
            const size_t ko = ((size_t)bn * FD + t0 + lr) * ED + lc;
            const size_t vo = ((size_t)bn * ED + lr) * FD + t0 + lc;
            *(uint4*)&sKh[lr * BSTR + lc] = *(const uint4*)&g_Kh[ko];
            *(uint4*)&sKh[lr * BSTR + lc + 8] = *(const uint4*)&g_Kh[ko + 8];
            *(uint4*)&sKl[lr * BSTR + lc] = *(const uint4*)&g_Kl[ko];
            *(uint4*)&sKl[lr * BSTR + lc + 8] = *(const uint4*)&g_Kl[ko + 8];
            *(uint4*)&sVh[lr * BSTR + lc] = *(const uint4*)&g_Vth[vo];
            *(uint4*)&sVh[lr * BSTR + lc + 8] = *(const uint4*)&g_Vth[vo + 8];
            *(uint4*)&sVl[lr * BSTR + lc] = *(const uint4*)&g_Vtl[vo];
            *(uint4*)&sVl[lr * BSTR + lc + 8] = *(const uint4*)&g_Vtl[vo + 8];
        }
        __syncthreads();

        // ---- S = Q K^T (3-term bf16 split) ----
        float sacc[4][4] = {};
        #pragma unroll
        for (int ks = 0; ks < 64; ks += 16) {
            uint32_t ahf[4], alf[4];
            ahf[0] = *(const uint32_t*)&sQh[r0 * BSTR + ks + bc];
            ahf[1] = *(const uint32_t*)&sQh[(r0 + 8) * BSTR + ks + bc];
            ahf[2] = *(const uint32_t*)&sQh[r0 * BSTR + ks + bc + 8];
            ahf[3] = *(const uint32_t*)&sQh[(r0 + 8) * BSTR + ks + bc + 8];
            alf[0] = *(const uint32_t*)&sQl[r0 * BSTR + ks + bc];
            alf[1] = *(const uint32_t*)&sQl[(r0 + 8) * BSTR + ks + bc];
            alf[2] = *(const uint32_t*)&sQl[r0 * BSTR + ks + bc + 8];
            alf[3] = *(const uint32_t*)&sQl[(r0 + 8) * BSTR + ks + bc + 8];
            #pragma unroll
            for (int ni = 0; ni < 4; ni++) {
                const int nr = wnw * 32 + ni * 8 + g;
                uint32_t bhf[2], blf[2];
                bhf[0] = *(const uint32_t*)&sKh[nr * BSTR + ks + bc];
                bhf[1] = *(const uint32_t*)&sKh[nr * BSTR + ks + bc + 8];
                blf[0] = *(const uint32_t*)&sKl[nr * BSTR + ks + bc];
                blf[1] = *(const uint32_t*)&sKl[nr * BSTR + ks + bc + 8];
                mma_bf16(sacc[ni], ahf, bhf);
                mma_bf16(sacc[ni], ahf, blf);
                mma_bf16(sacc[ni], alf, bhf);
            }
        }

        // ---- mask + scale -> Ss ----
        #pragma unroll
        for (int ni = 0; ni < 4; ni++) {
            const int col = wnw * 32 + ni * 8 + bc;
            const size_t mb0 = ((size_t)b * FD + f0 + r0) * FD + t0 + col;
            const size_t mb1 = mb0 + (size_t)8 * FD;
            float v0, v1, v2, v3;
            if (maskIsInt) {
                const int2 m0i = *(const int2*)((const int*)maskp + mb0);
                const int2 m1i = *(const int2*)((const int*)maskp + mb1);
                v0 = m0i.x ? sacc[ni][0] * scale : -10000.f;
                v1 = m0i.y ? sacc[ni][1] * scale : -10000.f;
                v2 = m1i.x ? sacc[ni][2] * scale : -10000.f;
                v3 = m1i.y ? sacc[ni][3] * scale : -10000.f;
            } else {
                const uchar2 m0c = *(const uchar2*)((const unsigned char*)maskp + mb0);
                const uchar2 m1c = *(const uchar2*)((const unsigned char*)maskp + mb1);
                v0 = m0c.x ? sacc[ni][0] * scale : -10000.f;
                v1 = m0c.y ? sacc[ni][1] * scale : -10000.f;
                v2 = m1c.x ? sacc[ni][2] * scale : -10000.f;
                v3 = m1c.y ? sacc[ni][3] * scale : -10000.f;
            }
            *(float2*)&Ss[r0 * SSTR + col] = make_float2(v0, v1);
            *(float2*)&Ss[(r0 + 8) * SSTR + col] = make_float2(v2, v3);
        }
        __syncthreads();

        // ---- online softmax; emit P as bf16 hi/lo ----
        {
            const int row = tid >> 2;
            const int seg = (tid & 3) << 4;
            float mx = -1e30f;
            #pragma unroll
            for (int j = 0; j < 16; j++) mx = fmaxf(mx, Ss[row * SSTR + seg + j]);
            mx = fmaxf(mx, __shfl_xor_sync(0xffffffffu, mx, 1));
            mx = fmaxf(mx, __shfl_xor_sync(0xffffffffu, mx, 2));
            const float m_old = m_s[row];
            const float m_new = fmaxf(m_old, mx);
            float sum = 0.f;
            #pragma unroll
            for (int j = 0; j < 16; j++) {
                const float p = __expf(Ss[row * SSTR + seg + j] - m_new);
                sum += p;
                const __nv_bfloat16 h = __float2bfloat16(p);
                const __nv_bfloat16 l = __float2bfloat16(p - __bfloat162float(h));
                sPh[row * BSTR + seg + j] = h;
                sPl[row * BSTR + seg + j] = l;
            }
            sum += __shfl_xor_sync(0xffffffffu, sum, 1);
            sum += __shfl_xor_sync(0xffffffffu, sum, 2);
            if ((tid & 3) == 0) {
                const float alpha = __expf(m_old - m_new);
                a_s[row] = alpha;
                l_s[row] = l_s[row] * alpha + sum;
                m_s[row] = m_new;
            }
        }
        __syncthreads();

        // ---- oacc = oacc*alpha + P V (3-term bf16 split) ----
        {
            const float a0 = a_s[r0], a1 = a_s[r0 + 8];
            #pragma unroll
            for (int ni = 0; ni < 4; ni++) {
                oacc[ni][0] *= a0; oacc[ni][1] *= a0;
                oacc[ni][2] *= a1; oacc[ni][3] *= a1;
            }
        }
        #pragma unroll
        for (int ks = 0; ks < 64; ks += 16) {
            uint32_t ahf[4], alf[4];
            ahf[0] = *(const uint32_t*)&sPh[r0 * BSTR + ks + bc];
            ahf[1] = *(const uint32_t*)&sPh[(r0 + 8) * BSTR + ks + bc];
            ahf[2] = *(const uint32_t*)&sPh[r0 * BSTR + ks + bc + 8];
            ahf[3] = *(const uint32_t*)&sPh[(r0 + 8) * BSTR + ks + bc + 8];
            alf[0] = *(const uint32_t*)&sPl[r0 * BSTR + ks + bc];
            alf[1] = *(const uint32_t*)&sPl[(r0 + 8) * BSTR + ks + bc];
            alf[2] = *(const uint32_t*)&sPl[r0 * BSTR + ks + bc + 8];
            alf[3] = *(const uint32_t*)&sPl[(r0 + 8) * BSTR + ks + bc + 8];
            #pragma unroll
            for (int ni = 0; ni < 4; ni++) {
                const int nr = wnw * 32 + ni * 8 + g;
                uint32_t bhf[2], blf[2];
                bhf[0] = *(const uint32_t*)&sVh[nr * BSTR + ks + bc];
                bhf[1] = *(const uint32_t*)&sVh[nr * BSTR + ks + bc + 8];
                blf[0] = *(const uint32_t*)&sVl[nr * BSTR + ks + bc];
                blf[1] = *(const uint32_t*)&sVl[nr * BSTR + ks + bc + 8];
                mma_bf16(oacc[ni], ahf, bhf);
                mma_bf16(oacc[ni], ahf, blf);
                mma_bf16(oacc[ni], alf, bhf);
            }
        }
    }

    // normalize + split-store ctx hi/lo (feeds out-proj GEMM directly)
    {
        const float inv0 = 1.0f / l_s[r0];
        const float inv1 = 1.0f / l_s[r0 + 8];
        #pragma unroll
        for (int ni = 0; ni < 4; ni++) {
            const int e = wnw * 32 + ni * 8 + bc;
            const size_t o0 = (size_t)((f0 + r0) * BD + b) * HD + n * 64 + e;
            const size_t o1 = (size_t)((f0 + r0 + 8) * BD + b) * HD + n * 64 + e;
            float x0 = oacc[ni][0] * inv0, x1 = oacc[ni][1] * inv0;
            float x2 = oacc[ni][2] * inv1, x3 = oacc[ni][3] * inv1;
            __nv_bfloat16 h0 = __float2bfloat16(x0), h1 = __float2bfloat16(x1);
            __nv_bfloat16 h2 = __float2bfloat16(x2), h3 = __float2bfloat16(x3);
            __nv_bfloat16 l0 = __float2bfloat16(x0 - __bfloat162float(h0));
            __nv_bfloat16 l1 = __float2bfloat16(x1 - __bfloat162float(h1));
            __nv_bfloat16 l2 = __float2bfloat16(x2 - __bfloat162float(h2));
            __nv_bfloat16 l3 = __float2bfloat16(x3 - __bfloat162float(h3));
            *(uint32_t*)&g_ctx_hi[o0] = pbf2(h0, h1);
            *(uint32_t*)&g_ctx_lo[o0] = pbf2(l0, l1);
            *(uint32_t*)&g_ctx_hi[o1] = pbf2(h2, h3);
            *(uint32_t*)&g_ctx_lo[o1] = pbf2(l2, l3);
        }
    }
}

// ---------------------------------------------------------------------------
__global__ void copy_tail_kernel(const float* __restrict__ src,
                                 float* __restrict__ dst, int count) {
    const int i = blockIdx.x * blockDim.x + threadIdx.x;
    if (i < count) dst[i] = src[i];
}

// ---------------------------------------------------------------------------
extern "C" void kernel_launch(void* const* d_in, const int* in_sizes, int n_in,
                              void* d_out, int out_size)
{
    const float* q_input = (const float*)d_in[0];
    const void*  mask    = d_in[1];
    const float* w_qkv   = (const float*)d_in[2];
    const float* b_qkv   = (const float*)d_in[3];
    const float* w_out   = (const float*)d_in[4];
    const float* b_out   = (const float*)d_in[5];
    float* out = (float*)d_out;

    float* qkv = nullptr;
    __nv_bfloat16 *wqh, *wql, *woh, *wol, *aqh, *aql, *cth, *ctl;
    cudaGetSymbolAddress((void**)&qkv, g_qkv);
    cudaGetSymbolAddress((void**)&wqh, g_wqkvT_hi);
    cudaGetSymbolAddress((void**)&wql, g_wqkvT_lo);
    cudaGetSymbolAddress((void**)&woh, g_woutT_hi);
    cudaGetSymbolAddress((void**)&wol, g_woutT_lo);
    cudaGetSymbolAddress((void**)&aqh, g_aq_hi);
    cudaGetSymbolAddress((void**)&aql, g_aq_lo);
    cudaGetSymbolAddress((void**)&cth, g_ctx_hi);
    cudaGetSymbolAddress((void**)&ctl, g_ctx_lo);

    // 0) mask dtype probe + input/weight splits
    detect_mask_kernel<<<1, 256>>>((const unsigned char*)mask);
    split_kernel<<<(MROWS * HD / 4 + 255) / 256, 256>>>(q_input, aqh, aql,
                                                        MROWS * HD / 4);
    transpose_split_kernel<<<dim3(D3 / 32, HD / 32), 256>>>(w_qkv, wqh, wql, HD, D3);
    transpose_split_kernel<<<dim3(HD / 32, HD / 32), 256>>>(w_out, woh, wol, HD, HD);

    // 1) QKV projection on tensor cores
    {
        dim3 grid(D3 / 128, MROWS / 128);
        mma_gemm_kernel<<<grid, 256>>>(aqh, aql, wqh, wql, b_qkv, qkv,
                                       MROWS, D3, HD);
    }

    // 1b) split QKV into per-head bf16 hi/lo arrays (V transposed)
    qkv_split_kernel<<<dim3(FD / 64, NBN), 256>>>(qkv);

    // 2) flash attention on tensor cores
    {
        cudaFuncSetAttribute(flash_attn_mma_kernel,
                             cudaFuncAttributeMaxDynamicSharedMemorySize,
                             FLASH_SMEM_BYTES);
        dim3 grid(FD / 64, NBN);
        flash_attn_mma_kernel<<<grid, 256, FLASH_SMEM_BYTES>>>(mask);
    }

    // 3) output projection on tensor cores (A = split ctx from flash)
    {
        dim3 grid(HD / 128, MROWS / 128);
        mma_gemm_kernel<<<grid, 256>>>(cth, ctl, woh, wol, nullptr, out,
                                       MROWS, HD, HD);
    }

    // 4) tuple tail: b_out appended after the [F,B,H] output
    const int main_elems = MROWS * HD;
    const int tail = out_size - main_elems;
    if (tail > 0) {
        copy_tail_kernel<<<(tail + 255) / 256, 256>>>(b_out, out + main_elems, tail);
    }
}

// round 15
// speedup vs baseline: 2.8008x; 1.2723x over previous
#include <cuda_runtime.h>
#include <cuda_bf16.h>
#include <cstdint>

// Problem dims (fixed by the reference)
#define FD 2048
#define BD 2
#define HD 1024
#define NH 16
#define ED 64
#define D3 3072          // 3*HD
#define MROWS 4096       // FD*BD
#define NBN 32           // BD*NH

// ---------------------------------------------------------------------------
// Scratch (static device globals — no allocations allowed)
// ---------------------------------------------------------------------------
__device__ float g_qkv[(size_t)MROWS * D3];                // QKV GEMM output fp32
__device__ __nv_bfloat16 g_wqkvT_hi[(size_t)D3 * HD];
__device__ __nv_bfloat16 g_wqkvT_lo[(size_t)D3 * HD];
__device__ __nv_bfloat16 g_woutT_hi[(size_t)HD * HD];
__device__ __nv_bfloat16 g_woutT_lo[(size_t)HD * HD];
__device__ __nv_bfloat16 g_aq_hi[(size_t)MROWS * HD];      // q_input split
__device__ __nv_bfloat16 g_aq_lo[(size_t)MROWS * HD];
__device__ __nv_bfloat16 g_Qh[(size_t)NBN * FD * ED];      // [bn][f][e] (pre-scaled)
__device__ __nv_bfloat16 g_Ql[(size_t)NBN * FD * ED];
__device__ __nv_bfloat16 g_Kh[(size_t)NBN * FD * ED];      // [bn][t][e]
__device__ __nv_bfloat16 g_Kl[(size_t)NBN * FD * ED];
__device__ __nv_bfloat16 g_Vth[(size_t)NBN * ED * FD];     // [bn][e][t]
__device__ __nv_bfloat16 g_Vtl[(size_t)NBN * ED * FD];
__device__ __nv_bfloat16 g_ctx_hi[(size_t)MROWS * HD];     // flash out, split
__device__ __nv_bfloat16 g_ctx_lo[(size_t)MROWS * HD];
__device__ int g_mask_is_int;

__device__ __forceinline__ uint32_t pbf2(__nv_bfloat16 a, __nv_bfloat16 b) {
    __nv_bfloat162 t = __halves2bfloat162(a, b);
    return *reinterpret_cast<uint32_t*>(&t);
}
__device__ __forceinline__ uint32_t pbf2f(float a, float b) {
    return pbf2(__float2bfloat16(a), __float2bfloat16(b));
}
__device__ __forceinline__ uint32_t pbf2lo(float a, float b) {
    __nv_bfloat16 ha = __float2bfloat16(a), hb = __float2bfloat16(b);
    return pbf2(__float2bfloat16(a - __bfloat162float(ha)),
                __float2bfloat16(b - __bfloat162float(hb)));
}

// m16n8k16 bf16 MMA, fp32 accumulate (HMMA path — no arch-suffix gating)
__device__ __forceinline__ void mma_bf16(float* d, const uint32_t* a,
                                         const uint32_t* b) {
    asm volatile(
        "mma.sync.aligned.m16n8k16.row.col.f32.bf16.bf16.f32 "
        "{%0,%1,%2,%3}, {%4,%5,%6,%7}, {%8,%9}, {%0,%1,%2,%3};"
        : "+f"(d[0]), "+f"(d[1]), "+f"(d[2]), "+f"(d[3])
        : "r"(a[0]), "r"(a[1]), "r"(a[2]), "r"(a[3]), "r"(b[0]), "r"(b[1]));
}

// ---------------------------------------------------------------------------
// Mask dtype detector: bool->uint8 vs bool->int32
// ---------------------------------------------------------------------------
__global__ void detect_mask_kernel(const unsigned char* __restrict__ m) {
    __shared__ int cnt;
    if (threadIdx.x == 0) cnt = 0;
    __syncthreads();
    int local = 0;
    for (int i = threadIdx.x; i < 65536; i += blockDim.x)
        if ((i & 3) && m[i]) local++;
    if (local) atomicAdd(&cnt, local);
    __syncthreads();
    if (threadIdx.x == 0) g_mask_is_int = (cnt == 0) ? 1 : 0;
}

// ---------------------------------------------------------------------------
// Elementwise fp32 -> hi/lo bf16 split (same layout)
// ---------------------------------------------------------------------------
__global__ void __launch_bounds__(256) split_kernel(
    const float* __restrict__ src, __nv_bfloat16* __restrict__ h,
    __nv_bfloat16* __restrict__ l, int count4)
{
    const int i = blockIdx.x * blockDim.x + threadIdx.x;
    if (i >= count4) return;
    const float4 x = ((const float4*)src)[i];
    ((uint2*)h)[i] = make_uint2(pbf2f(x.x, x.y), pbf2f(x.z, x.w));
    ((uint2*)l)[i] = make_uint2(pbf2lo(x.x, x.y), pbf2lo(x.z, x.w));
}

// ---------------------------------------------------------------------------
// Transpose + hi/lo bf16 split:  W[K,Nc] fp32 -> Th/Tl[Nc,K] bf16
// ---------------------------------------------------------------------------
__global__ void __launch_bounds__(256) transpose_split_kernel(
    const float* __restrict__ W, __nv_bfloat16* __restrict__ Th,
    __nv_bfloat16* __restrict__ Tl, int K, int Nc)
{
    __shared__ float tile[32][33];
    const int tx = threadIdx.x & 31, ty = threadIdx.x >> 5;
    const int n0 = blockIdx.x * 32, k0 = blockIdx.y * 32;
    #pragma unroll
    for (int j = 0; j < 32; j += 8)
        tile[ty + j][tx] = W[(size_t)(k0 + ty + j) * Nc + n0 + tx];
    __syncthreads();
    #pragma unroll
    for (int j = 0; j < 32; j += 8) {
        float v = tile[tx][ty + j];
        __nv_bfloat16 h = __float2bfloat16(v);
        __nv_bfloat16 l = __float2bfloat16(v - __bfloat162float(h));
        size_t o = (size_t)(n0 + ty + j) * K + k0 + tx;
        Th[o] = h;
        Tl[o] = l;
    }
}

// ---------------------------------------------------------------------------
// QKV postprocess: g_qkv fp32 -> per-head split arrays (Q pre-scaled, V^T).
// ---------------------------------------------------------------------------
__global__ void __launch_bounds__(256) qkv_split_kernel(
    const float* __restrict__ qkv)
{
    __shared__ __nv_bfloat16 vh[64][72], vl[64][72];
    const int tid = threadIdx.x;
    const int lr = tid >> 2;
    const int lc = (tid & 3) << 4;
    const int erot = tid & 3;
    const int bn = blockIdx.y;
    const int b = bn >> 4, n = bn & 15;
    const int f0 = blockIdx.x << 6;

    const float* src = qkv + (size_t)((f0 + lr) * BD + b) * D3 + n * 192;
    const size_t qko = ((size_t)bn * FD + f0 + lr) * ED + lc;

    float vv[16];
    #pragma unroll
    for (int c = 0; c < 16; c += 4) {
        // Q (fold scale = 1/8 exactly)
        float4 x = *(const float4*)&src[lc + c];
        x.x *= 0.125f; x.y *= 0.125f; x.z *= 0.125f; x.w *= 0.125f;
        *(uint2*)&g_Qh[qko + c] = make_uint2(pbf2f(x.x, x.y), pbf2f(x.z, x.w));
        *(uint2*)&g_Ql[qko + c] = make_uint2(pbf2lo(x.x, x.y), pbf2lo(x.z, x.w));
        // K
        x = *(const float4*)&src[64 + lc + c];
        *(uint2*)&g_Kh[qko + c] = make_uint2(pbf2f(x.x, x.y), pbf2f(x.z, x.w));
        *(uint2*)&g_Kl[qko + c] = make_uint2(pbf2lo(x.x, x.y), pbf2lo(x.z, x.w));
        // V (stage for transpose)
        float4 y = *(const float4*)&src[128 + lc + c];
        vv[c] = y.x; vv[c + 1] = y.y; vv[c + 2] = y.z; vv[c + 3] = y.w;
    }
    #pragma unroll
    for (int jj = 0; jj < 16; jj++) {
        const int j = (jj + (erot << 2)) & 15;
        const float v = vv[j];
        __nv_bfloat16 h = __float2bfloat16(v);
        vh[lc + j][lr] = h;
        vl[lc + j][lr] = __float2bfloat16(v - __bfloat162float(h));
    }
    __syncthreads();
    {
        const int er = tid >> 2;
        const int seg = (tid & 3) << 4;
        const size_t vo = ((size_t)bn * ED + er) * FD + f0 + seg;
        *(uint4*)&g_Vth[vo] = *(const uint4*)&vh[er][seg];
        *(uint4*)&g_Vth[vo + 8] = *(const uint4*)&vh[er][seg + 8];
        *(uint4*)&g_Vtl[vo] = *(const uint4*)&vl[er][seg];
        *(uint4*)&g_Vtl[vo + 8] = *(const uint4*)&vl[er][seg + 8];
    }
}

// ---------------------------------------------------------------------------
// mma.sync GEMM with pre-split A:  C[M,Nc] = A * BT^T (all bf16 hi/lo, 3-term)
// ---------------------------------------------------------------------------
#define ASTR 40

__global__ void __launch_bounds__(256) mma_gemm_kernel(
    const __nv_bfloat16* __restrict__ Ah_g,
    const __nv_bfloat16* __restrict__ Al_g,
    const __nv_bfloat16* __restrict__ BTh,
    const __nv_bfloat16* __restrict__ BTl,
    const float* __restrict__ bias,
    float* __restrict__ C, int M, int Nc, int K)
{
    __shared__ __nv_bfloat16 Ah[128][ASTR], Al[128][ASTR];
    __shared__ __nv_bfloat16 Bh[128][ASTR], Bl[128][ASTR];

    const int tid = threadIdx.x, wid = tid >> 5, lane = tid & 31;
    const int wm = wid & 1, wn = wid >> 1;
    const int m0 = blockIdx.y << 7, n0 = blockIdx.x << 7;
    const int bg = lane >> 2, bc = (lane & 3) << 1;

    const int lr = tid >> 1;
    const int lh = (tid & 1) << 4;
    const __nv_bfloat16* Ahp = Ah_g + (size_t)(m0 + lr) * K + lh;
    const __nv_bfloat16* Alp = Al_g + (size_t)(m0 + lr) * K + lh;
    const __nv_bfloat16* Bhp = BTh + (size_t)(n0 + lr) * K + lh;
    const __nv_bfloat16* Blp = BTl + (size_t)(n0 + lr) * K + lh;

    float acc[4][4][4] = {};

    for (int k0 = 0; k0 < K; k0 += 32) {
        __syncthreads();
        *(uint4*)&Ah[lr][lh] = *(const uint4*)(Ahp + k0);
        *(uint4*)&Ah[lr][lh + 8] = *(const uint4*)(Ahp + k0 + 8);
        *(uint4*)&Al[lr][lh] = *(const uint4*)(Alp + k0);
        *(uint4*)&Al[lr][lh + 8] = *(const uint4*)(Alp + k0 + 8);
        *(uint4*)&Bh[lr][lh] = *(const uint4*)(Bhp + k0);
        *(uint4*)&Bh[lr][lh + 8] = *(const uint4*)(Bhp + k0 + 8);
        *(uint4*)&Bl[lr][lh] = *(const uint4*)(Blp + k0);
        *(uint4*)&Bl[lr][lh + 8] = *(const uint4*)(Blp + k0 + 8);
        __syncthreads();

        #pragma unroll
        for (int ks = 0; ks < 32; ks += 16) {
            uint32_t bhf[4][2], blf[4][2];
            #pragma unroll
            for (int ni = 0; ni < 4; ni++) {
                const int nr = (wn << 5) + (ni << 3) + bg;
                bhf[ni][0] = *(const uint32_t*)&Bh[nr][ks + bc];
                bhf[ni][1] = *(const uint32_t*)&Bh[nr][ks + bc + 8];
                blf[ni][0] = *(const uint32_t*)&Bl[nr][ks + bc];
                blf[ni][1] = *(const uint32_t*)&Bl[nr][ks + bc + 8];
            }
            #pragma unroll
            for (int mi = 0; mi < 4; mi++) {
                const int ar = (wm << 6) + (mi << 4) + bg;
                uint32_t ahf[4], alf[4];
                ahf[0] = *(const uint32_t*)&Ah[ar][ks + bc];
                ahf[1] = *(const uint32_t*)&Ah[ar + 8][ks + bc];
                ahf[2] = *(const uint32_t*)&Ah[ar][ks + bc + 8];
                ahf[3] = *(const uint32_t*)&Ah[ar + 8][ks + bc + 8];
                alf[0] = *(const uint32_t*)&Al[ar][ks + bc];
                alf[1] = *(const uint32_t*)&Al[ar + 8][ks + bc];
                alf[2] = *(const uint32_t*)&Al[ar][ks + bc + 8];
                alf[3] = *(const uint32_t*)&Al[ar + 8][ks + bc + 8];
                #pragma unroll
                for (int ni = 0; ni < 4; ni++) {
                    mma_bf16(acc[mi][ni], ahf, bhf[ni]);
                    mma_bf16(acc[mi][ni], ahf, blf[ni]);
                    mma_bf16(acc[mi][ni], alf, bhf[ni]);
                }
            }
        }
    }

    #pragma unroll
    for (int mi = 0; mi < 4; mi++) {
        const int r0 = m0 + (wm << 6) + (mi << 4) + bg;
        #pragma unroll
        for (int ni = 0; ni < 4; ni++) {
            const int c = n0 + (wn << 5) + (ni << 3) + bc;
            float2 v0 = make_float2(acc[mi][ni][0], acc[mi][ni][1]);
            float2 v1 = make_float2(acc[mi][ni][2], acc[mi][ni][3]);
            if (bias) {
                const float2 bb = *(const float2*)&bias[c];
                v0.x += bb.x; v0.y += bb.y;
                v1.x += bb.x; v1.y += bb.y;
            }
            *(float2*)&C[(size_t)r0 * Nc + c] = v0;
            *(float2*)&C[(size_t)(r0 + 8) * Nc + c] = v1;
        }
    }
}

// ---------------------------------------------------------------------------
// Flash attention, register-resident softmax (FA2 style).
// One block per (128-row f-tile, bn). 8 warps; warp w owns rows w*16..w*16+15.
// S and P never touch smem; row stats live in registers (quad-shuffle reduce).
// ---------------------------------------------------------------------------
#define BSTR 72
#define FQ_B (128 * BSTR * 2)
#define FK_B (64 * BSTR * 2)
#define FO_QH 0
#define FO_QL (FO_QH + FQ_B)
#define FO_KH (FO_QL + FQ_B)
#define FO_KL (FO_KH + FK_B)
#define FO_VH (FO_KL + FK_B)
#define FO_VL (FO_VH + FK_B)
#define FLASH_SMEM_BYTES (FO_VL + FK_B)

__global__ void __launch_bounds__(256) flash_attn_mma_kernel(
    const void* __restrict__ maskp)
{
    extern __shared__ char smb[];
    __nv_bfloat16* sQh = (__nv_bfloat16*)(smb + FO_QH);
    __nv_bfloat16* sQl = (__nv_bfloat16*)(smb + FO_QL);
    __nv_bfloat16* sKh = (__nv_bfloat16*)(smb + FO_KH);
    __nv_bfloat16* sKl = (__nv_bfloat16*)(smb + FO_KL);
    __nv_bfloat16* sVh = (__nv_bfloat16*)(smb + FO_VH);   // [e][t]
    __nv_bfloat16* sVl = (__nv_bfloat16*)(smb + FO_VL);

    const int tid = threadIdx.x, wid = tid >> 5, lane = tid & 31;
    const int g = lane >> 2, bc = (lane & 3) << 1;
    const int bn = blockIdx.y;
    const int b = bn >> 4, n = bn & 15;
    const int f0 = blockIdx.x << 7;
    const int maskIsInt = g_mask_is_int;

    { // stage Q tile (128 rows) once: 2 threads/row, 32 bf16 each
        const int lr = tid >> 1;
        const int lh = (tid & 1) << 5;
        const size_t qo = ((size_t)bn * FD + f0 + lr) * ED + lh;
        #pragma unroll
        for (int c = 0; c < 32; c += 8) {
            *(uint4*)&sQh[lr * BSTR + lh + c] = *(const uint4*)&g_Qh[qo + c];
            *(uint4*)&sQl[lr * BSTR + lh + c] = *(const uint4*)&g_Ql[qo + c];
        }
    }

    const int r0 = (wid << 4) + g;          // lane's first row (local in 128)
    const size_t mrow0 = ((size_t)b * FD + f0 + r0) * FD;
    float oacc[8][4] = {};
    float m0 = -1e30f, m1 = -1e30f, l0 = 0.f, l1 = 0.f;

    for (int t0 = 0; t0 < FD; t0 += 64) {
        __syncthreads();   // prior PV done (also Q staged on first iter)
        { // K [t][e] rows, V^T [e][t] rows: 4 threads/row, 16 bf16 each
            const int lr = tid >> 2;
            const int lc = (tid & 3) << 4;
            const size_t ko = ((size_t)bn * FD + t0 + lr) * ED + lc;
            const size_t vo = ((size_t)bn * ED + lr) * FD + t0 + lc;
            *(uint4*)&sKh[lr * BSTR + lc] = *(const uint4*)&g_Kh[ko];
            *(uint4*)&sKh[lr * BSTR + lc + 8] = *(const uint4*)&g_Kh[ko + 8];
            *(uint4*)&sKl[lr * BSTR + lc] = *(const uint4*)&g_Kl[ko];
            *(uint4*)&sKl[lr * BSTR + lc + 8] = *(const uint4*)&g_Kl[ko + 8];
            *(uint4*)&sVh[lr * BSTR + lc] = *(const uint4*)&g_Vth[vo];
            *(uint4*)&sVh[lr * BSTR + lc + 8] = *(const uint4*)&g_Vth[vo + 8];
            *(uint4*)&sVl[lr * BSTR + lc] = *(const uint4*)&g_Vtl[vo];
            *(uint4*)&sVl[lr * BSTR + lc + 8] = *(const uint4*)&g_Vtl[vo + 8];
        }
        __syncthreads();

        // ---- S = Q K^T (3-term), warp covers 16 rows x 64 cols ----
        float s[8][4] = {};
        #pragma unroll
        for (int ks = 0; ks < 64; ks += 16) {
            uint32_t ahf[4], alf[4];
            ahf[0] = *(const uint32_t*)&sQh[r0 * BSTR + ks + bc];
            ahf[1] = *(const uint32_t*)&sQh[(r0 + 8) * BSTR + ks + bc];
            ahf[2] = *(const uint32_t*)&sQh[r0 * BSTR + ks + bc + 8];
            ahf[3] = *(const uint32_t*)&sQh[(r0 + 8) * BSTR + ks + bc + 8];
            alf[0] = *(const uint32_t*)&sQl[r0 * BSTR + ks + bc];
            alf[1] = *(const uint32_t*)&sQl[(r0 + 8) * BSTR + ks + bc];
            alf[2] = *(const uint32_t*)&sQl[r0 * BSTR + ks + bc + 8];
            alf[3] = *(const uint32_t*)&sQl[(r0 + 8) * BSTR + ks + bc + 8];
            #pragma unroll
            for (int ni = 0; ni < 8; ni++) {
                const int nr = (ni << 3) + g;
                uint32_t bhf[2], blf[2];
                bhf[0] = *(const uint32_t*)&sKh[nr * BSTR + ks + bc];
                bhf[1] = *(const uint32_t*)&sKh[nr * BSTR + ks + bc + 8];
                blf[0] = *(const uint32_t*)&sKl[nr * BSTR + ks + bc];
                blf[1] = *(const uint32_t*)&sKl[nr * BSTR + ks + bc + 8];
                mma_bf16(s[ni], ahf, bhf);
                mma_bf16(s[ni], ahf, blf);
                mma_bf16(s[ni], alf, bhf);
            }
        }

        // ---- mask (scale already folded into Q) ----
        #pragma unroll
        for (int ni = 0; ni < 8; ni++) {
            const int col = (ni << 3) + bc;
            const size_t mb0 = mrow0 + t0 + col;
            const size_t mb1 = mb0 + (size_t)8 * FD;
            if (maskIsInt) {
                const int2 ma = *(const int2*)((const int*)maskp + mb0);
                const int2 mbv = *(const int2*)((const int*)maskp + mb1);
                if (!ma.x) s[ni][0] = -10000.f;
                if (!ma.y) s[ni][1] = -10000.f;
                if (!mbv.x) s[ni][2] = -10000.f;
                if (!mbv.y) s[ni][3] = -10000.f;
            } else {
                const uchar2 ma = *(const uchar2*)((const unsigned char*)maskp + mb0);
                const uchar2 mbv = *(const uchar2*)((const unsigned char*)maskp + mb1);
                if (!ma.x) s[ni][0] = -10000.f;
                if (!ma.y) s[ni][1] = -10000.f;
                if (!mbv.x) s[ni][2] = -10000.f;
                if (!mbv.y) s[ni][3] = -10000.f;
            }
        }

        // ---- register softmax (quad shuffle reduce; lanes of a quad share g) --
        float mx0 = -1e30f, mx1 = -1e30f;
        #pragma unroll
        for (int ni = 0; ni < 8; ni++) {
            mx0 = fmaxf(mx0, fmaxf(s[ni][0], s[ni][1]));
            mx1 = fmaxf(mx1, fmaxf(s[ni][2], s[ni][3]));
        }
        mx0 = fmaxf(mx0, __shfl_xor_sync(0xffffffffu, mx0, 1));
        mx0 = fmaxf(mx0, __shfl_xor_sync(0xffffffffu, mx0, 2));
        mx1 = fmaxf(mx1, __shfl_xor_sync(0xffffffffu, mx1, 1));
        mx1 = fmaxf(mx1, __shfl_xor_sync(0xffffffffu, mx1, 2));
        const float mn0 = fmaxf(m0, mx0), mn1 = fmaxf(m1, mx1);
        const float al0 = __expf(m0 - mn0), al1 = __expf(m1 - mn1);
        m0 = mn0; m1 = mn1;

        uint32_t ph[8][2], pl[8][2];
        float sum0 = 0.f, sum1 = 0.f;
        #pragma unroll
        for (int ni = 0; ni < 8; ni++) {
            const float p0 = __expf(s[ni][0] - mn0);
            const float p1 = __expf(s[ni][1] - mn0);
            const float p2 = __expf(s[ni][2] - mn1);
            const float p3 = __expf(s[ni][3] - mn1);
            sum0 += p0 + p1; sum1 += p2 + p3;
            ph[ni][0] = pbf2f(p0, p1);  ph[ni][1] = pbf2f(p2, p3);
            pl[ni][0] = pbf2lo(p0, p1); pl[ni][1] = pbf2lo(p2, p3);
        }
        sum0 += __shfl_xor_sync(0xffffffffu, sum0, 1);
        sum0 += __shfl_xor_sync(0xffffffffu, sum0, 2);
        sum1 += __shfl_xor_sync(0xffffffffu, sum1, 1);
        sum1 += __shfl_xor_sync(0xffffffffu, sum1, 2);
        l0 = l0 * al0 + sum0;
        l1 = l1 * al1 + sum1;

        #pragma unroll
        for (int ni = 0; ni < 8; ni++) {
            oacc[ni][0] *= al0; oacc[ni][1] *= al0;
            oacc[ni][2] *= al1; oacc[ni][3] *= al1;
        }

        // ---- PV: P fragments straight from registers (acc->A same mapping) --
        #pragma unroll
        for (int c = 0; c < 4; c++) {
            uint32_t ahf[4], alf[4];
            ahf[0] = ph[2*c][0];   ahf[1] = ph[2*c][1];
            ahf[2] = ph[2*c+1][0]; ahf[3] = ph[2*c+1][1];
            alf[0] = pl[2*c][0];   alf[1] = pl[2*c][1];
            alf[2] = pl[2*c+1][0]; alf[3] = pl[2*c+1][1];
            const int ks = c << 4;
            #pragma unroll
            for (int ni = 0; ni < 8; ni++) {
                const int nr = (ni << 3) + g;       // e-row of V^T
                uint32_t bhf[2], blf[2];
                bhf[0] = *(const uint32_t*)&sVh[nr * BSTR + ks + bc];
                bhf[1] = *(const uint32_t*)&sVh[nr * BSTR + ks + bc + 8];
                blf[0] = *(const uint32_t*)&sVl[nr * BSTR + ks + bc];
                blf[1] = *(const uint32_t*)&sVl[nr * BSTR + ks + bc + 8];
                mma_bf16(oacc[ni], ahf, bhf);
                mma_bf16(oacc[ni], ahf, blf);
                mma_bf16(oacc[ni], alf, bhf);
            }
        }
    }

    // normalize + split-store ctx hi/lo (feeds out-proj GEMM directly)
    {
        const float inv0 = 1.0f / l0;
        const float inv1 = 1.0f / l1;
        #pragma unroll
        for (int ni = 0; ni < 8; ni++) {
            const int e = (ni << 3) + bc;
            const size_t o0 = (size_t)((f0 + r0) * BD + b) * HD + n * 64 + e;
            const size_t o1 = (size_t)((f0 + r0 + 8) * BD + b) * HD + n * 64 + e;
            const float x0 = oacc[ni][0] * inv0, x1 = oacc[ni][1] * inv0;
            const float x2 = oacc[ni][2] * inv1, x3 = oacc[ni][3] * inv1;
            *(uint32_t*)&g_ctx_hi[o0] = pbf2f(x0, x1);
            *(uint32_t*)&g_ctx_lo[o0] = pbf2lo(x0, x1);
            *(uint32_t*)&g_ctx_hi[o1] = pbf2f(x2, x3);
            *(uint32_t*)&g_ctx_lo[o1] = pbf2lo(x2, x3);
        }
    }
}

// ---------------------------------------------------------------------------
__global__ void copy_tail_kernel(const float* __restrict__ src,
                                 float* __restrict__ dst, int count) {
    const int i = blockIdx.x * blockDim.x + threadIdx.x;
    if (i < count) dst[i] = src[i];
}

// ---------------------------------------------------------------------------
extern "C" void kernel_launch(void* const* d_in, const int* in_sizes, int n_in,
                              void* d_out, int out_size)
{
    const float* q_input = (const float*)d_in[0];
    const void*  mask    = d_in[1];
    const float* w_qkv   = (const float*)d_in[2];
    const float* b_qkv   = (const float*)d_in[3];
    const float* w_out   = (const float*)d_in[4];
    const float* b_out   = (const float*)d_in[5];
    float* out = (float*)d_out;

    float* qkv = nullptr;
    __nv_bfloat16 *wqh, *wql, *woh, *wol, *aqh, *aql, *cth, *ctl;
    cudaGetSymbolAddress((void**)&qkv, g_qkv);
    cudaGetSymbolAddress((void**)&wqh, g_wqkvT_hi);
    cudaGetSymbolAddress((void**)&wql, g_wqkvT_lo);
    cudaGetSymbolAddress((void**)&woh, g_woutT_hi);
    cudaGetSymbolAddress((void**)&wol, g_woutT_lo);
    cudaGetSymbolAddress((void**)&aqh, g_aq_hi);
    cudaGetSymbolAddress((void**)&aql, g_aq_lo);
    cudaGetSymbolAddress((void**)&cth, g_ctx_hi);
    cudaGetSymbolAddress((void**)&ctl, g_ctx_lo);

    // 0) mask dtype probe + input/weight splits
    detect_mask_kernel<<<1, 256>>>((const unsigned char*)mask);
    split_kernel<<<(MROWS * HD / 4 + 255) / 256, 256>>>(q_input, aqh, aql,
                                                        MROWS * HD / 4);
    transpose_split_kernel<<<dim3(D3 / 32, HD / 32), 256>>>(w_qkv, wqh, wql, HD, D3);
    transpose_split_kernel<<<dim3(HD / 32, HD / 32), 256>>>(w_out, woh, wol, HD, HD);

    // 1) QKV projection on tensor cores
    {
        dim3 grid(D3 / 128, MROWS / 128);
        mma_gemm_kernel<<<grid, 256>>>(aqh, aql, wqh, wql, b_qkv, qkv,
                                       MROWS, D3, HD);
    }

    // 1b) split QKV into per-head bf16 hi/lo arrays (Q scaled, V transposed)
    qkv_split_kernel<<<dim3(FD / 64, NBN), 256>>>(qkv);

    // 2) flash attention on tensor cores (register softmax)
    {
        cudaFuncSetAttribute(flash_attn_mma_kernel,
                             cudaFuncAttributeMaxDynamicSharedMemorySize,
                             FLASH_SMEM_BYTES);
        dim3 grid(FD / 128, NBN);
        flash_attn_mma_kernel<<<grid, 256, FLASH_SMEM_BYTES>>>(mask);
    }

    // 3) output projection on tensor cores (A = split ctx from flash)
    {
        dim3 grid(HD / 128, MROWS / 128);
        mma_gemm_kernel<<<grid, 256>>>(cth, ctl, woh, wol, nullptr, out,
                                       MROWS, HD, HD);
    }

    // 4) tuple tail: b_out appended after the [F,B,H] output
    const int main_elems = MROWS * HD;
    const int tail = out_size - main_elems;
    if (tail > 0) {
        copy_tail_kernel<<<(tail + 255) / 256, 256>>>(b_out, out + main_elems, tail);
    }
}